// round 6
// baseline (speedup 1.0000x reference)
#include <cuda_runtime.h>
#include <cuda_bf16.h>
#include <math.h>
#include <stdint.h>

typedef unsigned long long ull;

#define QN 48
#define KN 48
#define SS 192
#define DH 512
#define NL 3
#define DFFN 2048
#define NP (QN*KN)   /* 2304 */
#define KC 1536      /* concatenated K dim: [hi|hi|lo] x [hi|lo|hi] */
#define ROWB 3072    /* bytes per row = KC * 2 */

// ---------------- scratch (device globals) ----------------
__device__ uint4  g_Qc[(size_t)NL*QN*SS*ROWB/16];   // 84.9 MB bf16 triplets (query)
__device__ uint4  g_Kc[(size_t)NL*KN*SS*ROWB/16];   // 84.9 MB bf16 triplets (key)
__device__ float g_G [NL * SS * SS];
__device__ float g_X [NL * NP * 2 * SS];
__device__ float g_Z [NL * NP * 2];

// ---------------- packed f32x2 helpers ----------------
__device__ __forceinline__ ull fma2(ull a, ull b, ull c) {
    ull d; asm("fma.rn.f32x2 %0, %1, %2, %3;" : "=l"(d) : "l"(a), "l"(b), "l"(c)); return d;
}
__device__ __forceinline__ ull pack2(float x, float y) {
    ull d; asm("mov.b64 %0, {%1, %2};" : "=l"(d) : "f"(x), "f"(y)); return d;
}
__device__ __forceinline__ void unpack2(ull v, float& x, float& y) {
    asm("mov.b64 {%0, %1}, %2;" : "=f"(x), "=f"(y) : "l"(v));
}
__device__ __forceinline__ uint32_t smem_u32(const void* p) {
    uint32_t a;
    asm("{ .reg .u64 t; cvta.to.shared.u64 t, %1; cvt.u32.u64 %0, t; }" : "=r"(a) : "l"(p));
    return a;
}
// sign-aware float atomic max (int order == float order for >=0; reversed unsigned for <0)
__device__ __forceinline__ void atomicMaxFloat(float* addr, float val) {
    if (val >= 0.0f) atomicMax((int*)addr, __float_as_int(val));
    else             atomicMin((unsigned int*)addr, (unsigned int)__float_as_int(val));
}

// ---------------- mma / ldmatrix wrappers ----------------
__device__ __forceinline__ void mma_bf16(float* d, const uint32_t* a, uint32_t b0, uint32_t b1) {
    asm volatile("mma.sync.aligned.m16n8k16.row.col.f32.bf16.bf16.f32 "
                 "{%0,%1,%2,%3}, {%4,%5,%6,%7}, {%8,%9}, {%0,%1,%2,%3};"
                 : "+f"(d[0]), "+f"(d[1]), "+f"(d[2]), "+f"(d[3])
                 : "r"(a[0]), "r"(a[1]), "r"(a[2]), "r"(a[3]), "r"(b0), "r"(b1));
}
__device__ __forceinline__ void ldsm_x4(uint32_t* r, uint32_t addr) {
    asm volatile("ldmatrix.sync.aligned.m8n8.x4.shared.b16 {%0,%1,%2,%3}, [%4];"
                 : "=r"(r[0]), "=r"(r[1]), "=r"(r[2]), "=r"(r[3]) : "r"(addr));
}

// ---------------- kernel 1: gate sigmoid + zero Z + init row-max to -inf ----------------
__global__ void gate_init_kernel(const float* __restrict__ se) {
    int idx = blockIdx.x * blockDim.x + threadIdx.x;
    if (idx < NL * SS * SS) g_G[idx] = 1.0f / (1.0f + expf(-se[idx]));
    if (idx < NL * NP * 2)  g_Z[idx] = 0.0f;
    if (idx < NL * NP * SS) {
        int pair = idx / SS, off = idx - pair * SS;
        g_X[(size_t)pair * 2 * SS + off] = -3.402823466e38f;
    }
}

// ---------------- kernel 2: projection GEMM -> bf16 hi/lo triplets ----------------
__global__ void __launch_bounds__(256)
proj_gemm_kernel(const float* __restrict__ A, const float* __restrict__ W,
                 const float* __restrict__ bias, int dst)
{
    const int i = blockIdx.z;
    const int LDA = NL * DH;
    const float* Ab = A + i * DH;
    const float* Wb = W + (size_t)i * DH * DH;
    const float* bb = bias + i * DH;
    char* outBase = (char*)(dst ? g_Kc : g_Qc) + (size_t)(i * QN * SS) * ROWB;
    const int m0 = blockIdx.y * 128, n0 = blockIdx.x * 128;

    __shared__ __align__(16) float As[16 * 132];
    __shared__ __align__(16) float Bs[16 * 132];

    const int tid = threadIdx.x;
    const int tx = tid & 15, ty = tid >> 4;

    ull acc[8][4];
#pragma unroll
    for (int r = 0; r < 8; r++)
#pragma unroll
        for (int j = 0; j < 4; j++) acc[r][j] = 0ull;

    for (int k0 = 0; k0 < DH; k0 += 16) {
#pragma unroll
        for (int l = 0; l < 2; l++) {
            int idx = tid + l * 256;
            int r = idx >> 2, e4 = idx & 3;
            float4 va = *(const float4*)(Ab + (size_t)(m0 + r) * LDA + k0 + e4 * 4);
            float4 vb = *(const float4*)(Wb + (size_t)(n0 + r) * DH  + k0 + e4 * 4);
            int d = e4 * 4;
            As[(d + 0) * 132 + r] = va.x; As[(d + 1) * 132 + r] = va.y;
            As[(d + 2) * 132 + r] = va.z; As[(d + 3) * 132 + r] = va.w;
            Bs[(d + 0) * 132 + r] = vb.x; Bs[(d + 1) * 132 + r] = vb.y;
            Bs[(d + 2) * 132 + r] = vb.z; Bs[(d + 3) * 132 + r] = vb.w;
        }
        __syncthreads();
#pragma unroll
        for (int d = 0; d < 16; d++) {
            const float* ap = As + d * 132 + ty * 8;
            const float* bp = Bs + d * 132 + tx * 8;
            float4 a0 = *(const float4*)ap;
            float4 a1 = *(const float4*)(ap + 4);
            ulonglong2 bq0 = *(const ulonglong2*)bp;
            ulonglong2 bq1 = *(const ulonglong2*)(bp + 4);
            ull b[4] = { bq0.x, bq0.y, bq1.x, bq1.y };
            float a[8] = { a0.x, a0.y, a0.z, a0.w, a1.x, a1.y, a1.z, a1.w };
#pragma unroll
            for (int r = 0; r < 8; r++) {
                ull ad = pack2(a[r], a[r]);
#pragma unroll
                for (int j = 0; j < 4; j++) acc[r][j] = fma2(ad, b[j], acc[r][j]);
            }
        }
        __syncthreads();
    }

    float bv[8];
#pragma unroll
    for (int j = 0; j < 8; j++) bv[j] = bb[n0 + tx * 8 + j];
#pragma unroll
    for (int r = 0; r < 8; r++) {
        int row = m0 + ty * 8 + r;
        float v[8];
        unpack2(acc[r][0], v[0], v[1]); unpack2(acc[r][1], v[2], v[3]);
        unpack2(acc[r][2], v[4], v[5]); unpack2(acc[r][3], v[6], v[7]);
        uint32_t hi[4], lo[4];
#pragma unroll
        for (int j = 0; j < 4; j++) {
            float a = v[2*j]   + bv[2*j];
            float b = v[2*j+1] + bv[2*j+1];
            float ha = __bfloat162float(__float2bfloat16(a));
            float hb = __bfloat162float(__float2bfloat16(b));
            __nv_bfloat162 h = __floats2bfloat162_rn(ha, hb);
            __nv_bfloat162 l = __floats2bfloat162_rn(a - ha, b - hb);
            hi[j] = *reinterpret_cast<uint32_t*>(&h);
            lo[j] = *reinterpret_cast<uint32_t*>(&l);
        }
        uint4 H = { hi[0], hi[1], hi[2], hi[3] };
        uint4 L = { lo[0], lo[1], lo[2], lo[3] };
        char* rp = outBase + (size_t)row * ROWB + (size_t)(n0 + tx * 8) * 2;
        *(uint4*)(rp)        = H;                 // slot 0: hi
        if (dst == 0) {                           // query: [hi, hi, lo]
            *(uint4*)(rp + 1024) = H;
            *(uint4*)(rp + 2048) = L;
        } else {                                  // key:   [hi, lo, hi]
            *(uint4*)(rp + 1024) = L;
            *(uint4*)(rp + 2048) = H;
        }
    }
}

// ---------------- kernel 3: HMMA score GEMM + gate + dual max-pool ----------------
// 2 CTAs per (q,k,i): each 192 threads / 6 warps computes 192 x 96 (N split).
#define STAGES 3
#define CHUNK_B 128          /* 64 bf16 per row per chunk */
#define NCHUNK 24            /* 3072 B / 128 B */
#define TILE_A 24576         /* A: 192 rows x 128B; B (96 rows) follows */
#define STAGE_BYTES 36864    /* (192 + 96) * 128 */
#define SM_BASE 1024
#define SMEM_TOTAL_SCORE (SM_BASE + STAGES * STAGE_BYTES)   /* 111616 */

__global__ void __launch_bounds__(192, 2)
score_mma_kernel()
{
    extern __shared__ __align__(128) char dsm[];
    const int i = blockIdx.z, q = blockIdx.y;
    const int k = blockIdx.x >> 1;
    const int h = blockIdx.x & 1;          // N half: cols [h*96, h*96+96)
    const int tid = threadIdx.x;
    const int wid = tid >> 5;
    const int lane = tid & 31;
    uint32_t sb = smem_u32(dsm);

    const char* aG = (const char*)g_Qc + (size_t)((i * QN + q) * SS) * ROWB;
    const char* bG = (const char*)g_Kc + (size_t)((i * KN + k) * SS + h * 96) * ROWB;

    // warp tile: 64 rows x 48 cols. 6 warps = 3 (m) x 2 (n).
    const int mw = wid >> 1, nw = wid & 1;
    const int m0 = mw * 64;
    const int n0 = nw * 48;               // local col within the 96-wide half

    // swizzled ldmatrix lane offsets (stage-relative); k-step advances via ^ (ks<<5)
    uint32_t baseA[4], baseB[3];
#pragma unroll
    for (int mi = 0; mi < 4; mi++) {
        uint32_t row = (uint32_t)(m0 + mi * 16 + (lane & 15));
        uint32_t off = row * 128 + ((lane >> 4) << 4);
        baseA[mi] = off ^ ((off >> 3) & 0x70);
    }
#pragma unroll
    for (int nt = 0; nt < 3; nt++) {
        uint32_t row = (uint32_t)(n0 + nt * 16 + (lane & 7) + ((lane >> 4) << 3));
        uint32_t off = row * 128 + (((lane >> 3) & 1) << 4);
        baseB[nt] = TILE_A + (off ^ ((off >> 3) & 0x70));
    }

    float acc[4][6][4];
#pragma unroll
    for (int mi = 0; mi < 4; mi++)
#pragma unroll
        for (int ni = 0; ni < 6; ni++)
#pragma unroll
            for (int j = 0; j < 4; j++) acc[mi][ni][j] = 0.0f;

    // producer: A (192 rows) + B (96 rows), 64-col chunk, SW128 swizzle
    auto load_stage = [&](int c, int st) {
        uint32_t base = sb + SM_BASE + st * STAGE_BYTES;
#pragma unroll
        for (int l = 0; l < 12; l++) {
            int idx = tid + l * 192;            // 0..2303 16B units
            int isB = idx >= 1536;
            int j2 = isB ? idx - 1536 : idx;
            int r = j2 >> 3, g = j2 & 7;
            uint32_t off = (uint32_t)(r * 128 + g * 16);
            off ^= (off >> 3) & 0x70;
            uint32_t dst = base + (isB ? TILE_A : 0) + off;
            const void* src = (const void*)((isB ? bG : aG) + (size_t)r * ROWB + c * CHUNK_B + g * 16);
            asm volatile("cp.async.cg.shared.global [%0], [%1], 16;" :: "r"(dst), "l"(src) : "memory");
        }
        asm volatile("cp.async.commit_group;" ::: "memory");
    };

    load_stage(0, 0);
    load_stage(1, 1);

    int stc = 0;        // stage holding chunk it
    int stl = 2;        // stage to load chunk it+2 into
    for (int it = 0; it < NCHUNK; it++) {
        if (it == NCHUNK - 1) asm volatile("cp.async.wait_group 0;" ::: "memory");
        else                  asm volatile("cp.async.wait_group 1;" ::: "memory");
        __syncthreads();                      // publish chunk it; all done computing it-1
        if (it + 2 < NCHUNK) load_stage(it + 2, stl);

        uint32_t stage = sb + SM_BASE + stc * STAGE_BYTES;
#pragma unroll
        for (int ks = 0; ks < 4; ks++) {
            uint32_t kx = (uint32_t)(ks << 5);
            uint32_t a[4][4], b[3][4];
#pragma unroll
            for (int mi = 0; mi < 4; mi++) ldsm_x4(a[mi], stage + (baseA[mi] ^ kx));
#pragma unroll
            for (int nt = 0; nt < 3; nt++) ldsm_x4(b[nt], stage + (baseB[nt] ^ kx));
#pragma unroll
            for (int mi = 0; mi < 4; mi++) {
#pragma unroll
                for (int nt = 0; nt < 3; nt++) {
                    mma_bf16(acc[mi][2 * nt],     a[mi], b[nt][0], b[nt][1]);
                    mma_bf16(acc[mi][2 * nt + 1], a[mi], b[nt][2], b[nt][3]);
                }
            }
        }
        if (++stc == STAGES) stc = 0;
        if (++stl == STAGES) stl = 0;
    }

    // ---- epilogue: gate + dual max-pool (score[t][s], gate[s][t]) ----
    const float* gb = g_G + (size_t)i * SS * SS;
    const int g8 = lane >> 2, t4 = lane & 3;
    float rmax[8], cmax[12];
#pragma unroll
    for (int j = 0; j < 8; j++)  rmax[j] = -3.402823466e38f;
#pragma unroll
    for (int j = 0; j < 12; j++) cmax[j] = -3.402823466e38f;

#pragma unroll
    for (int mi = 0; mi < 4; mi++) {
        int r0 = m0 + mi * 16 + g8;
        int r1 = r0 + 8;
#pragma unroll
        for (int ni = 0; ni < 6; ni++) {
            int c0 = h * 96 + n0 + ni * 8 + t4 * 2;   // global s
            int c1 = c0 + 1;
            float v00 = acc[mi][ni][0] * __ldg(gb + (size_t)c0 * SS + r0);
            float v01 = acc[mi][ni][1] * __ldg(gb + (size_t)c1 * SS + r0);
            float v10 = acc[mi][ni][2] * __ldg(gb + (size_t)c0 * SS + r1);
            float v11 = acc[mi][ni][3] * __ldg(gb + (size_t)c1 * SS + r1);
            rmax[mi * 2]     = fmaxf(rmax[mi * 2],     fmaxf(v00, v01));
            rmax[mi * 2 + 1] = fmaxf(rmax[mi * 2 + 1], fmaxf(v10, v11));
            cmax[ni * 2]     = fmaxf(cmax[ni * 2],     fmaxf(v00, v10));
            cmax[ni * 2 + 1] = fmaxf(cmax[ni * 2 + 1], fmaxf(v01, v11));
        }
    }
    // rows shared across t4 (lanes ^1, ^2); cols shared across g8 (lanes ^4, ^8, ^16)
#pragma unroll
    for (int m = 1; m <= 2; m <<= 1)
#pragma unroll
        for (int j = 0; j < 8; j++)
            rmax[j] = fmaxf(rmax[j], __shfl_xor_sync(0xffffffffu, rmax[j], m));
#pragma unroll
    for (int m = 4; m <= 16; m <<= 1)
#pragma unroll
        for (int j = 0; j < 12; j++)
            cmax[j] = fmaxf(cmax[j], __shfl_xor_sync(0xffffffffu, cmax[j], m));

    float* red1 = (float*)(dsm + SM_BASE);          // [2][192] by nw (stage-0 area, chunk-21 data dead)
    float* red2 = red1 + 2 * SS;                    // [3][96] by mw
    if (t4 == 0) {
#pragma unroll
        for (int j = 0; j < 8; j++)
            red1[nw * SS + m0 + (j >> 1) * 16 + g8 + (j & 1) * 8] = rmax[j];
    }
    if (g8 == 0) {
#pragma unroll
        for (int j = 0; j < 12; j++)
            red2[mw * 96 + n0 + (j >> 1) * 8 + t4 * 2 + (j & 1)] = cmax[j];
    }
    __syncthreads();

    float* xo = g_X + ((size_t)i * NP + (size_t)q * KN + k) * (2 * SS);
    {
        float m = fmaxf(red1[tid], red1[SS + tid]);      // partial over this half's 96 cols
        atomicMaxFloat(&xo[tid], m);
    }
    if (tid < 96) {
        float m = fmaxf(fmaxf(red2[tid], red2[96 + tid]), red2[192 + tid]);
        xo[SS + h * 96 + tid] = m;                       // complete over all 192 rows
    }
}

// ---------------- kernel 4: bn1 -> fc2 -> bn2 -> relu -> fc3 row-reduce ----------------
__global__ void __launch_bounds__(256)
mlp_kernel(const float* __restrict__ w2, const float* __restrict__ b2,
           const float* __restrict__ g2, const float* __restrict__ bb2,
           const float* __restrict__ w3,
           const float* __restrict__ g1, const float* __restrict__ bb1)
{
    const int i = blockIdx.z;
    const int row0 = blockIdx.y * 64;
    const int col0 = blockIdx.x * 128;
    const float scale = 1.0f / sqrtf(1.0f + 1e-5f);
    const float g1c = g1[i] * scale, b1v = bb1[i];
    const float* Xb  = g_X + (size_t)i * NP * 2 * SS;
    const float* W2b = w2  + (size_t)i * DFFN * SS;

    __shared__ __align__(16) float As[16 * 68];
    __shared__ __align__(16) float Bs[16 * 132];
    __shared__ float zsh[64];

    const int tid = threadIdx.x;
    const int tx = tid & 15, ty = tid >> 4;
    if (tid < 64) zsh[tid] = 0.0f;

    ull acc[4][4];
#pragma unroll
    for (int r = 0; r < 4; r++)
#pragma unroll
        for (int j = 0; j < 4; j++) acc[r][j] = 0ull;

    for (int k0 = 0; k0 < SS; k0 += 16) {
        {
            int r = tid >> 2, e4 = tid & 3;
            float4 va = *(const float4*)(Xb + (size_t)(row0 + r) * SS + k0 + e4 * 4);
            va.x = va.x * g1c + b1v; va.y = va.y * g1c + b1v;
            va.z = va.z * g1c + b1v; va.w = va.w * g1c + b1v;
            int d = e4 * 4;
            As[(d + 0) * 68 + r] = va.x; As[(d + 1) * 68 + r] = va.y;
            As[(d + 2) * 68 + r] = va.z; As[(d + 3) * 68 + r] = va.w;
        }
#pragma unroll
        for (int l = 0; l < 2; l++) {
            int idx = tid + l * 256;
            int c = idx >> 2, e4 = idx & 3;
            float4 vb = *(const float4*)(W2b + (size_t)(col0 + c) * SS + k0 + e4 * 4);
            int d = e4 * 4;
            Bs[(d + 0) * 132 + c] = vb.x; Bs[(d + 1) * 132 + c] = vb.y;
            Bs[(d + 2) * 132 + c] = vb.z; Bs[(d + 3) * 132 + c] = vb.w;
        }
        __syncthreads();
#pragma unroll
        for (int d = 0; d < 16; d++) {
            const float* ap = As + d * 68 + ty * 4;
            const float* bp = Bs + d * 132 + tx * 8;
            float4 a0 = *(const float4*)ap;
            ulonglong2 bq0 = *(const ulonglong2*)bp;
            ulonglong2 bq1 = *(const ulonglong2*)(bp + 4);
            ull b[4] = { bq0.x, bq0.y, bq1.x, bq1.y };
            float a[4] = { a0.x, a0.y, a0.z, a0.w };
#pragma unroll
            for (int r = 0; r < 4; r++) {
                ull ad = pack2(a[r], a[r]);
#pragma unroll
                for (int j = 0; j < 4; j++) acc[r][j] = fma2(ad, b[j], acc[r][j]);
            }
        }
        __syncthreads();
    }

    const int cb = col0 + tx * 8;
    float b2v[8], g2v[8], bb2v[8], w3v[8];
    {
        const float4* p;
        p = (const float4*)(b2  + (size_t)i * DFFN + cb);
        float4 u0 = p[0], u1 = p[1];
        b2v[0]=u0.x; b2v[1]=u0.y; b2v[2]=u0.z; b2v[3]=u0.w;
        b2v[4]=u1.x; b2v[5]=u1.y; b2v[6]=u1.z; b2v[7]=u1.w;
        p = (const float4*)(g2  + (size_t)i * DFFN + cb);
        u0 = p[0]; u1 = p[1];
        g2v[0]=u0.x; g2v[1]=u0.y; g2v[2]=u0.z; g2v[3]=u0.w;
        g2v[4]=u1.x; g2v[5]=u1.y; g2v[6]=u1.z; g2v[7]=u1.w;
        p = (const float4*)(bb2 + (size_t)i * DFFN + cb);
        u0 = p[0]; u1 = p[1];
        bb2v[0]=u0.x; bb2v[1]=u0.y; bb2v[2]=u0.z; bb2v[3]=u0.w;
        bb2v[4]=u1.x; bb2v[5]=u1.y; bb2v[6]=u1.z; bb2v[7]=u1.w;
        p = (const float4*)(w3  + (size_t)i * DFFN + cb);
        u0 = p[0]; u1 = p[1];
        w3v[0]=u0.x; w3v[1]=u0.y; w3v[2]=u0.z; w3v[3]=u0.w;
        w3v[4]=u1.x; w3v[5]=u1.y; w3v[6]=u1.z; w3v[7]=u1.w;
    }

#pragma unroll
    for (int r = 0; r < 4; r++) {
        float zp = 0.0f;
#pragma unroll
        for (int j = 0; j < 4; j++) {
            float y0, y1;
            unpack2(acc[r][j], y0, y1);
            y0 += b2v[2 * j];     y1 += b2v[2 * j + 1];
            float yb0 = y0 * (g2v[2 * j] * scale)     + bb2v[2 * j];
            float yb1 = y1 * (g2v[2 * j + 1] * scale) + bb2v[2 * j + 1];
            if (yb0 > 0.0f) zp += yb0 * w3v[2 * j];
            if (yb1 > 0.0f) zp += yb1 * w3v[2 * j + 1];
        }
        atomicAdd(&zsh[ty * 4 + r], zp);
    }
    __syncthreads();
    if (tid < 64) atomicAdd(&g_Z[(size_t)i * NP * 2 + row0 + tid], zsh[tid]);
}

// ---------------- kernel 5: pair-sum, bn3, layer-sum, decoder norm ----------------
__global__ void final_kernel(const float* __restrict__ fc3_b,
                             const float* __restrict__ bn3_g, const float* __restrict__ bn3_b,
                             const float* __restrict__ norm_g, const float* __restrict__ norm_b,
                             float* __restrict__ out)
{
    int p = blockIdx.x * blockDim.x + threadIdx.x;
    if (p >= NP) return;
    const float scale = 1.0f / sqrtf(1.0f + 1e-5f);
    float acc = 0.0f;
#pragma unroll
    for (int i = 0; i < NL; i++) {
        float u = g_Z[i * NP * 2 + 2 * p] + g_Z[i * NP * 2 + 2 * p + 1] + 2.0f * fc3_b[i];
        acc += u * (bn3_g[i] * scale) + bn3_b[i];
    }
    out[p] = acc * (norm_g[0] * scale) + norm_b[0];
}

// ---------------- launch ----------------
extern "C" void kernel_launch(void* const* d_in, const int* in_sizes, int n_in,
                              void* d_out, int out_size)
{
    (void)in_sizes; (void)n_in; (void)out_size;
    const float* memory_  = (const float*)d_in[0];
    const float* features = (const float*)d_in[1];
    const float* fc1_w  = (const float*)d_in[2];
    const float* fc1_b  = (const float*)d_in[3];
    const float* se     = (const float*)d_in[4];
    const float* bn1_g  = (const float*)d_in[5];
    const float* bn1_b  = (const float*)d_in[6];
    const float* fc2_w  = (const float*)d_in[7];
    const float* fc2_b  = (const float*)d_in[8];
    const float* bn2_g  = (const float*)d_in[9];
    const float* bn2_b  = (const float*)d_in[10];
    const float* fc3_w  = (const float*)d_in[11];
    const float* fc3_b  = (const float*)d_in[12];
    const float* bn3_g  = (const float*)d_in[13];
    const float* bn3_b  = (const float*)d_in[14];
    const float* norm_g = (const float*)d_in[15];
    const float* norm_b = (const float*)d_in[16];
    float* out = (float*)d_out;

    cudaFuncSetAttribute(score_mma_kernel,
                         cudaFuncAttributeMaxDynamicSharedMemorySize, SMEM_TOTAL_SCORE);

    gate_init_kernel<<<(NL * NP * SS + 255) / 256, 256>>>(se);

    dim3 gproj(DH / 128, (QN * SS) / 128, NL);
    proj_gemm_kernel<<<gproj, 256>>>(memory_,  fc1_w, fc1_b, 0);
    proj_gemm_kernel<<<gproj, 256>>>(features, fc1_w, fc1_b, 1);

    score_mma_kernel<<<dim3(KN * 2, QN, NL), 192, SMEM_TOTAL_SCORE>>>();

    mlp_kernel<<<dim3(DFFN / 128, (2 * NP) / 64, NL), 256>>>(
        fc2_w, fc2_b, bn2_g, bn2_b, fc3_w, bn1_g, bn1_b);

    final_kernel<<<(NP + 255) / 256, 256>>>(fc3_b, bn3_g, bn3_b, norm_g, norm_b, out);
}

// round 7
// speedup vs baseline: 1.2532x; 1.2532x over previous
#include <cuda_runtime.h>
#include <cuda_bf16.h>
#include <cuda_fp16.h>
#include <math.h>
#include <stdint.h>

typedef unsigned long long ull;

#define QN 48
#define KN 48
#define SS 192
#define DH 512
#define NL 3
#define DFFN 2048
#define NP (QN*KN)   /* 2304 */
#define KC 1024      /* concatenated K dim: [xh|xl] x [yh|yh] fp16 */
#define ROWB 2048    /* bytes per row = KC * 2 */

// ---------------- scratch (device globals) ----------------
__device__ uint4  g_Qc[(size_t)NL*QN*SS*ROWB/16];   // 56.6 MB fp16 [hi|lo] (query)
__device__ uint4  g_Kc[(size_t)NL*KN*SS*ROWB/16];   // 56.6 MB fp16 [hi|hi] (key)
__device__ float g_G [NL * SS * SS];
__device__ float g_X [NL * NP * 2 * SS];
__device__ float g_Z [NL * NP * 2];

// ---------------- packed f32x2 helpers ----------------
__device__ __forceinline__ ull fma2(ull a, ull b, ull c) {
    ull d; asm("fma.rn.f32x2 %0, %1, %2, %3;" : "=l"(d) : "l"(a), "l"(b), "l"(c)); return d;
}
__device__ __forceinline__ ull pack2(float x, float y) {
    ull d; asm("mov.b64 %0, {%1, %2};" : "=l"(d) : "f"(x), "f"(y)); return d;
}
__device__ __forceinline__ void unpack2(ull v, float& x, float& y) {
    asm("mov.b64 {%0, %1}, %2;" : "=f"(x), "=f"(y) : "l"(v));
}
__device__ __forceinline__ uint32_t smem_u32(const void* p) {
    uint32_t a;
    asm("{ .reg .u64 t; cvta.to.shared.u64 t, %1; cvt.u32.u64 %0, t; }" : "=r"(a) : "l"(p));
    return a;
}
// sign-aware float atomic max
__device__ __forceinline__ void atomicMaxFloat(float* addr, float val) {
    if (val >= 0.0f) atomicMax((int*)addr, __float_as_int(val));
    else             atomicMin((unsigned int*)addr, (unsigned int)__float_as_int(val));
}

// ---------------- mma / ldmatrix wrappers ----------------
__device__ __forceinline__ void mma_fp16(float* d, const uint32_t* a, uint32_t b0, uint32_t b1) {
    asm volatile("mma.sync.aligned.m16n8k16.row.col.f32.f16.f16.f32 "
                 "{%0,%1,%2,%3}, {%4,%5,%6,%7}, {%8,%9}, {%0,%1,%2,%3};"
                 : "+f"(d[0]), "+f"(d[1]), "+f"(d[2]), "+f"(d[3])
                 : "r"(a[0]), "r"(a[1]), "r"(a[2]), "r"(a[3]), "r"(b0), "r"(b1));
}
__device__ __forceinline__ void ldsm_x4(uint32_t* r, uint32_t addr) {
    asm volatile("ldmatrix.sync.aligned.m8n8.x4.shared.b16 {%0,%1,%2,%3}, [%4];"
                 : "=r"(r[0]), "=r"(r[1]), "=r"(r[2]), "=r"(r[3]) : "r"(addr));
}

// ---------------- kernel 1: gate sigmoid + zero Z + init row-max ----------------
__global__ void gate_init_kernel(const float* __restrict__ se) {
    int idx = blockIdx.x * blockDim.x + threadIdx.x;
    if (idx < NL * SS * SS) g_G[idx] = 1.0f / (1.0f + expf(-se[idx]));
    if (idx < NL * NP * 2)  g_Z[idx] = 0.0f;
    if (idx < NL * NP * SS) {
        int pair = idx / SS, off = idx - pair * SS;
        g_X[(size_t)pair * 2 * SS + off] = -3.402823466e38f;
    }
}

// ---------------- kernel 2: projection GEMM -> fp16 hi/lo pairs ----------------
__global__ void __launch_bounds__(256)
proj_gemm_kernel(const float* __restrict__ A, const float* __restrict__ W,
                 const float* __restrict__ bias, int dst)
{
    const int i = blockIdx.z;
    const int LDA = NL * DH;
    const float* Ab = A + i * DH;
    const float* Wb = W + (size_t)i * DH * DH;
    const float* bb = bias + i * DH;
    char* outBase = (char*)(dst ? g_Kc : g_Qc) + (size_t)(i * QN * SS) * ROWB;
    const int m0 = blockIdx.y * 128, n0 = blockIdx.x * 128;

    __shared__ __align__(16) float As[16 * 132];
    __shared__ __align__(16) float Bs[16 * 132];

    const int tid = threadIdx.x;
    const int tx = tid & 15, ty = tid >> 4;

    ull acc[8][4];
#pragma unroll
    for (int r = 0; r < 8; r++)
#pragma unroll
        for (int j = 0; j < 4; j++) acc[r][j] = 0ull;

    for (int k0 = 0; k0 < DH; k0 += 16) {
#pragma unroll
        for (int l = 0; l < 2; l++) {
            int idx = tid + l * 256;
            int r = idx >> 2, e4 = idx & 3;
            float4 va = *(const float4*)(Ab + (size_t)(m0 + r) * LDA + k0 + e4 * 4);
            float4 vb = *(const float4*)(Wb + (size_t)(n0 + r) * DH  + k0 + e4 * 4);
            int d = e4 * 4;
            As[(d + 0) * 132 + r] = va.x; As[(d + 1) * 132 + r] = va.y;
            As[(d + 2) * 132 + r] = va.z; As[(d + 3) * 132 + r] = va.w;
            Bs[(d + 0) * 132 + r] = vb.x; Bs[(d + 1) * 132 + r] = vb.y;
            Bs[(d + 2) * 132 + r] = vb.z; Bs[(d + 3) * 132 + r] = vb.w;
        }
        __syncthreads();
#pragma unroll
        for (int d = 0; d < 16; d++) {
            const float* ap = As + d * 132 + ty * 8;
            const float* bp = Bs + d * 132 + tx * 8;
            float4 a0 = *(const float4*)ap;
            float4 a1 = *(const float4*)(ap + 4);
            ulonglong2 bq0 = *(const ulonglong2*)bp;
            ulonglong2 bq1 = *(const ulonglong2*)(bp + 4);
            ull b[4] = { bq0.x, bq0.y, bq1.x, bq1.y };
            float a[8] = { a0.x, a0.y, a0.z, a0.w, a1.x, a1.y, a1.z, a1.w };
#pragma unroll
            for (int r = 0; r < 8; r++) {
                ull ad = pack2(a[r], a[r]);
#pragma unroll
                for (int j = 0; j < 4; j++) acc[r][j] = fma2(ad, b[j], acc[r][j]);
            }
        }
        __syncthreads();
    }

    float bv[8];
#pragma unroll
    for (int j = 0; j < 8; j++) bv[j] = bb[n0 + tx * 8 + j];
#pragma unroll
    for (int r = 0; r < 8; r++) {
        int row = m0 + ty * 8 + r;
        float v[8];
        unpack2(acc[r][0], v[0], v[1]); unpack2(acc[r][1], v[2], v[3]);
        unpack2(acc[r][2], v[4], v[5]); unpack2(acc[r][3], v[6], v[7]);
        uint32_t hi[4], lo[4];
#pragma unroll
        for (int j = 0; j < 4; j++) {
            float a = v[2*j]   + bv[2*j];
            float b = v[2*j+1] + bv[2*j+1];
            __half ha = __float2half_rn(a);
            __half hb = __float2half_rn(b);
            __half2 h = __halves2half2(ha, hb);
            __half2 l = __floats2half2_rn(a - __half2float(ha), b - __half2float(hb));
            hi[j] = *reinterpret_cast<uint32_t*>(&h);
            lo[j] = *reinterpret_cast<uint32_t*>(&l);
        }
        uint4 H = { hi[0], hi[1], hi[2], hi[3] };
        uint4 L = { lo[0], lo[1], lo[2], lo[3] };
        char* rp = outBase + (size_t)row * ROWB + (size_t)(n0 + tx * 8) * 2;
        *(uint4*)(rp) = H;                        // slot 0: hi
        if (dst == 0) *(uint4*)(rp + 1024) = L;   // query: [hi, lo]
        else          *(uint4*)(rp + 1024) = H;   // key:   [hi, hi]
    }
}

// ---------------- kernel 3: HMMA score GEMM + gate + dual max-pool ----------------
// 2 CTAs per (q,k,i): each 192 threads / 6 warps computes 192 x 96 (N split).
#define STAGES 3
#define CHUNK_B 128          /* 64 fp16 per row per chunk */
#define NCHUNK 16            /* 2048 B / 128 B */
#define TILE_A 24576         /* A: 192 rows x 128B; B (96 rows) follows */
#define STAGE_BYTES 36864    /* (192 + 96) * 128 */
#define SM_BASE 1024
#define SMEM_TOTAL_SCORE (SM_BASE + STAGES * STAGE_BYTES)   /* 111616 */

__global__ void __launch_bounds__(192, 2)
score_mma_kernel()
{
    extern __shared__ __align__(128) char dsm[];
    const int i = blockIdx.z, q = blockIdx.y;
    const int k = blockIdx.x >> 1;
    const int h = blockIdx.x & 1;          // N half: cols [h*96, h*96+96)
    const int tid = threadIdx.x;
    const int wid = tid >> 5;
    const int lane = tid & 31;
    uint32_t sb = smem_u32(dsm);

    const char* aG = (const char*)g_Qc + (size_t)((i * QN + q) * SS) * ROWB;
    const char* bG = (const char*)g_Kc + (size_t)((i * KN + k) * SS + h * 96) * ROWB;

    // warp tile: 64 rows x 48 cols. 6 warps = 3 (m) x 2 (n).
    const int mw = wid >> 1, nw = wid & 1;
    const int m0 = mw * 64;
    const int n0 = nw * 48;               // local col within the 96-wide half

    uint32_t baseA[4], baseB[3];
#pragma unroll
    for (int mi = 0; mi < 4; mi++) {
        uint32_t row = (uint32_t)(m0 + mi * 16 + (lane & 15));
        uint32_t off = row * 128 + ((lane >> 4) << 4);
        baseA[mi] = off ^ ((off >> 3) & 0x70);
    }
#pragma unroll
    for (int nt = 0; nt < 3; nt++) {
        uint32_t row = (uint32_t)(n0 + nt * 16 + (lane & 7) + ((lane >> 4) << 3));
        uint32_t off = row * 128 + (((lane >> 3) & 1) << 4);
        baseB[nt] = TILE_A + (off ^ ((off >> 3) & 0x70));
    }

    float acc[4][6][4];
#pragma unroll
    for (int mi = 0; mi < 4; mi++)
#pragma unroll
        for (int ni = 0; ni < 6; ni++)
#pragma unroll
            for (int j = 0; j < 4; j++) acc[mi][ni][j] = 0.0f;

    // producer: A (192 rows) + B (96 rows), 64-col chunk, SW128 swizzle
    auto load_stage = [&](int c, int st) {
        uint32_t base = sb + SM_BASE + st * STAGE_BYTES;
#pragma unroll
        for (int l = 0; l < 12; l++) {
            int idx = tid + l * 192;            // 0..2303 16B units
            int isB = idx >= 1536;
            int j2 = isB ? idx - 1536 : idx;
            int r = j2 >> 3, g = j2 & 7;
            uint32_t off = (uint32_t)(r * 128 + g * 16);
            off ^= (off >> 3) & 0x70;
            uint32_t dst = base + (isB ? TILE_A : 0) + off;
            const void* src = (const void*)((isB ? bG : aG) + (size_t)r * ROWB + c * CHUNK_B + g * 16);
            asm volatile("cp.async.cg.shared.global [%0], [%1], 16;" :: "r"(dst), "l"(src) : "memory");
        }
        asm volatile("cp.async.commit_group;" ::: "memory");
    };

    load_stage(0, 0);
    load_stage(1, 1);

    int stc = 0;        // stage holding chunk it
    int stl = 2;        // stage to load chunk it+2 into
    for (int it = 0; it < NCHUNK; it++) {
        if (it == NCHUNK - 1) asm volatile("cp.async.wait_group 0;" ::: "memory");
        else                  asm volatile("cp.async.wait_group 1;" ::: "memory");
        __syncthreads();                      // publish chunk it; all done computing it-1
        if (it + 2 < NCHUNK) load_stage(it + 2, stl);

        uint32_t stage = sb + SM_BASE + stc * STAGE_BYTES;
#pragma unroll
        for (int ks = 0; ks < 4; ks++) {
            uint32_t kx = (uint32_t)(ks << 5);
            uint32_t a[4][4], b[3][4];
#pragma unroll
            for (int mi = 0; mi < 4; mi++) ldsm_x4(a[mi], stage + (baseA[mi] ^ kx));
#pragma unroll
            for (int nt = 0; nt < 3; nt++) ldsm_x4(b[nt], stage + (baseB[nt] ^ kx));
#pragma unroll
            for (int mi = 0; mi < 4; mi++) {
#pragma unroll
                for (int nt = 0; nt < 3; nt++) {
                    mma_fp16(acc[mi][2 * nt],     a[mi], b[nt][0], b[nt][1]);
                    mma_fp16(acc[mi][2 * nt + 1], a[mi], b[nt][2], b[nt][3]);
                }
            }
        }
        if (++stc == STAGES) stc = 0;
        if (++stl == STAGES) stl = 0;
    }

    // ---- epilogue: gate + dual max-pool (score[t][s], gate[s][t]) ----
    const float* gb = g_G + (size_t)i * SS * SS;
    const int g8 = lane >> 2, t4 = lane & 3;
    float rmax[8], cmax[12];
#pragma unroll
    for (int j = 0; j < 8; j++)  rmax[j] = -3.402823466e38f;
#pragma unroll
    for (int j = 0; j < 12; j++) cmax[j] = -3.402823466e38f;

#pragma unroll
    for (int mi = 0; mi < 4; mi++) {
        int r0 = m0 + mi * 16 + g8;
        int r1 = r0 + 8;
#pragma unroll
        for (int ni = 0; ni < 6; ni++) {
            int c0 = h * 96 + n0 + ni * 8 + t4 * 2;   // global s
            int c1 = c0 + 1;
            float v00 = acc[mi][ni][0] * __ldg(gb + (size_t)c0 * SS + r0);
            float v01 = acc[mi][ni][1] * __ldg(gb + (size_t)c1 * SS + r0);
            float v10 = acc[mi][ni][2] * __ldg(gb + (size_t)c0 * SS + r1);
            float v11 = acc[mi][ni][3] * __ldg(gb + (size_t)c1 * SS + r1);
            rmax[mi * 2]     = fmaxf(rmax[mi * 2],     fmaxf(v00, v01));
            rmax[mi * 2 + 1] = fmaxf(rmax[mi * 2 + 1], fmaxf(v10, v11));
            cmax[ni * 2]     = fmaxf(cmax[ni * 2],     fmaxf(v00, v10));
            cmax[ni * 2 + 1] = fmaxf(cmax[ni * 2 + 1], fmaxf(v01, v11));
        }
    }
#pragma unroll
    for (int m = 1; m <= 2; m <<= 1)
#pragma unroll
        for (int j = 0; j < 8; j++)
            rmax[j] = fmaxf(rmax[j], __shfl_xor_sync(0xffffffffu, rmax[j], m));
#pragma unroll
    for (int m = 4; m <= 16; m <<= 1)
#pragma unroll
        for (int j = 0; j < 12; j++)
            cmax[j] = fmaxf(cmax[j], __shfl_xor_sync(0xffffffffu, cmax[j], m));

    float* red1 = (float*)(dsm + SM_BASE);          // [2][192] by nw
    float* red2 = red1 + 2 * SS;                    // [3][96] by mw
    if (t4 == 0) {
#pragma unroll
        for (int j = 0; j < 8; j++)
            red1[nw * SS + m0 + (j >> 1) * 16 + g8 + (j & 1) * 8] = rmax[j];
    }
    if (g8 == 0) {
#pragma unroll
        for (int j = 0; j < 12; j++)
            red2[mw * 96 + n0 + (j >> 1) * 8 + t4 * 2 + (j & 1)] = cmax[j];
    }
    __syncthreads();

    float* xo = g_X + ((size_t)i * NP + (size_t)q * KN + k) * (2 * SS);
    {
        float m = fmaxf(red1[tid], red1[SS + tid]);      // partial over this half's 96 cols
        atomicMaxFloat(&xo[tid], m);
    }
    if (tid < 96) {
        float m = fmaxf(fmaxf(red2[tid], red2[96 + tid]), red2[192 + tid]);
        xo[SS + h * 96 + tid] = m;                       // complete over all 192 rows
    }
}

// ---------------- kernel 4: bn1 -> fc2 -> bn2 -> relu -> fc3 row-reduce ----------------
__global__ void __launch_bounds__(256)
mlp_kernel(const float* __restrict__ w2, const float* __restrict__ b2,
           const float* __restrict__ g2, const float* __restrict__ bb2,
           const float* __restrict__ w3,
           const float* __restrict__ g1, const float* __restrict__ bb1)
{
    const int i = blockIdx.z;
    const int row0 = blockIdx.y * 64;
    const int col0 = blockIdx.x * 128;
    const float scale = 1.0f / sqrtf(1.0f + 1e-5f);
    const float g1c = g1[i] * scale, b1v = bb1[i];
    const float* Xb  = g_X + (size_t)i * NP * 2 * SS;
    const float* W2b = w2  + (size_t)i * DFFN * SS;

    __shared__ __align__(16) float As[16 * 68];
    __shared__ __align__(16) float Bs[16 * 132];
    __shared__ float zsh[64];

    const int tid = threadIdx.x;
    const int tx = tid & 15, ty = tid >> 4;
    if (tid < 64) zsh[tid] = 0.0f;

    ull acc[4][4];
#pragma unroll
    for (int r = 0; r < 4; r++)
#pragma unroll
        for (int j = 0; j < 4; j++) acc[r][j] = 0ull;

    for (int k0 = 0; k0 < SS; k0 += 16) {
        {
            int r = tid >> 2, e4 = tid & 3;
            float4 va = *(const float4*)(Xb + (size_t)(row0 + r) * SS + k0 + e4 * 4);
            va.x = va.x * g1c + b1v; va.y = va.y * g1c + b1v;
            va.z = va.z * g1c + b1v; va.w = va.w * g1c + b1v;
            int d = e4 * 4;
            As[(d + 0) * 68 + r] = va.x; As[(d + 1) * 68 + r] = va.y;
            As[(d + 2) * 68 + r] = va.z; As[(d + 3) * 68 + r] = va.w;
        }
#pragma unroll
        for (int l = 0; l < 2; l++) {
            int idx = tid + l * 256;
            int c = idx >> 2, e4 = idx & 3;
            float4 vb = *(const float4*)(W2b + (size_t)(col0 + c) * SS + k0 + e4 * 4);
            int d = e4 * 4;
            Bs[(d + 0) * 132 + c] = vb.x; Bs[(d + 1) * 132 + c] = vb.y;
            Bs[(d + 2) * 132 + c] = vb.z; Bs[(d + 3) * 132 + c] = vb.w;
        }
        __syncthreads();
#pragma unroll
        for (int d = 0; d < 16; d++) {
            const float* ap = As + d * 68 + ty * 4;
            const float* bp = Bs + d * 132 + tx * 8;
            float4 a0 = *(const float4*)ap;
            ulonglong2 bq0 = *(const ulonglong2*)bp;
            ulonglong2 bq1 = *(const ulonglong2*)(bp + 4);
            ull b[4] = { bq0.x, bq0.y, bq1.x, bq1.y };
            float a[4] = { a0.x, a0.y, a0.z, a0.w };
#pragma unroll
            for (int r = 0; r < 4; r++) {
                ull ad = pack2(a[r], a[r]);
#pragma unroll
                for (int j = 0; j < 4; j++) acc[r][j] = fma2(ad, b[j], acc[r][j]);
            }
        }
        __syncthreads();
    }

    const int cb = col0 + tx * 8;
    float b2v[8], g2v[8], bb2v[8], w3v[8];
    {
        const float4* p;
        p = (const float4*)(b2  + (size_t)i * DFFN + cb);
        float4 u0 = p[0], u1 = p[1];
        b2v[0]=u0.x; b2v[1]=u0.y; b2v[2]=u0.z; b2v[3]=u0.w;
        b2v[4]=u1.x; b2v[5]=u1.y; b2v[6]=u1.z; b2v[7]=u1.w;
        p = (const float4*)(g2  + (size_t)i * DFFN + cb);
        u0 = p[0]; u1 = p[1];
        g2v[0]=u0.x; g2v[1]=u0.y; g2v[2]=u0.z; g2v[3]=u0.w;
        g2v[4]=u1.x; g2v[5]=u1.y; g2v[6]=u1.z; g2v[7]=u1.w;
        p = (const float4*)(bb2 + (size_t)i * DFFN + cb);
        u0 = p[0]; u1 = p[1];
        bb2v[0]=u0.x; bb2v[1]=u0.y; bb2v[2]=u0.z; bb2v[3]=u0.w;
        bb2v[4]=u1.x; bb2v[5]=u1.y; bb2v[6]=u1.z; bb2v[7]=u1.w;
        p = (const float4*)(w3  + (size_t)i * DFFN + cb);
        u0 = p[0]; u1 = p[1];
        w3v[0]=u0.x; w3v[1]=u0.y; w3v[2]=u0.z; w3v[3]=u0.w;
        w3v[4]=u1.x; w3v[5]=u1.y; w3v[6]=u1.z; w3v[7]=u1.w;
    }

#pragma unroll
    for (int r = 0; r < 4; r++) {
        float zp = 0.0f;
#pragma unroll
        for (int j = 0; j < 4; j++) {
            float y0, y1;
            unpack2(acc[r][j], y0, y1);
            y0 += b2v[2 * j];     y1 += b2v[2 * j + 1];
            float yb0 = y0 * (g2v[2 * j] * scale)     + bb2v[2 * j];
            float yb1 = y1 * (g2v[2 * j + 1] * scale) + bb2v[2 * j + 1];
            if (yb0 > 0.0f) zp += yb0 * w3v[2 * j];
            if (yb1 > 0.0f) zp += yb1 * w3v[2 * j + 1];
        }
        atomicAdd(&zsh[ty * 4 + r], zp);
    }
    __syncthreads();
    if (tid < 64) atomicAdd(&g_Z[(size_t)i * NP * 2 + row0 + tid], zsh[tid]);
}

// ---------------- kernel 5: pair-sum, bn3, layer-sum, decoder norm ----------------
__global__ void final_kernel(const float* __restrict__ fc3_b,
                             const float* __restrict__ bn3_g, const float* __restrict__ bn3_b,
                             const float* __restrict__ norm_g, const float* __restrict__ norm_b,
                             float* __restrict__ out)
{
    int p = blockIdx.x * blockDim.x + threadIdx.x;
    if (p >= NP) return;
    const float scale = 1.0f / sqrtf(1.0f + 1e-5f);
    float acc = 0.0f;
#pragma unroll
    for (int i = 0; i < NL; i++) {
        float u = g_Z[i * NP * 2 + 2 * p] + g_Z[i * NP * 2 + 2 * p + 1] + 2.0f * fc3_b[i];
        acc += u * (bn3_g[i] * scale) + bn3_b[i];
    }
    out[p] = acc * (norm_g[0] * scale) + norm_b[0];
}

// ---------------- launch ----------------
extern "C" void kernel_launch(void* const* d_in, const int* in_sizes, int n_in,
                              void* d_out, int out_size)
{
    (void)in_sizes; (void)n_in; (void)out_size;
    const float* memory_  = (const float*)d_in[0];
    const float* features = (const float*)d_in[1];
    const float* fc1_w  = (const float*)d_in[2];
    const float* fc1_b  = (const float*)d_in[3];
    const float* se     = (const float*)d_in[4];
    const float* bn1_g  = (const float*)d_in[5];
    const float* bn1_b  = (const float*)d_in[6];
    const float* fc2_w  = (const float*)d_in[7];
    const float* fc2_b  = (const float*)d_in[8];
    const float* bn2_g  = (const float*)d_in[9];
    const float* bn2_b  = (const float*)d_in[10];
    const float* fc3_w  = (const float*)d_in[11];
    const float* fc3_b  = (const float*)d_in[12];
    const float* bn3_g  = (const float*)d_in[13];
    const float* bn3_b  = (const float*)d_in[14];
    const float* norm_g = (const float*)d_in[15];
    const float* norm_b = (const float*)d_in[16];
    float* out = (float*)d_out;

    cudaFuncSetAttribute(score_mma_kernel,
                         cudaFuncAttributeMaxDynamicSharedMemorySize, SMEM_TOTAL_SCORE);

    gate_init_kernel<<<(NL * NP * SS + 255) / 256, 256>>>(se);

    dim3 gproj(DH / 128, (QN * SS) / 128, NL);
    proj_gemm_kernel<<<gproj, 256>>>(memory_,  fc1_w, fc1_b, 0);
    proj_gemm_kernel<<<gproj, 256>>>(features, fc1_w, fc1_b, 1);

    score_mma_kernel<<<dim3(KN * 2, QN, NL), 192, SMEM_TOTAL_SCORE>>>();

    mlp_kernel<<<dim3(DFFN / 128, (2 * NP) / 64, NL), 256>>>(
        fc2_w, fc2_b, bn2_g, bn2_b, fc3_w, bn1_g, bn1_b);

    final_kernel<<<(NP + 255) / 256, 256>>>(fc3_b, bn3_g, bn3_b, norm_g, norm_b, out);
}

// round 8
// speedup vs baseline: 1.6757x; 1.3372x over previous
#include <cuda_runtime.h>
#include <cuda_bf16.h>
#include <cuda_fp16.h>
#include <math.h>
#include <stdint.h>

typedef unsigned long long ull;

#define QN 48
#define KN 48
#define SS 192
#define DH 512
#define NL 3
#define DFFN 2048
#define NP (QN*KN)   /* 2304 */
#define KC 512       /* single fp16: K = D */
#define ROWB 1024    /* bytes per row = KC * 2 */

// ---------------- scratch (device globals) ----------------
__device__ uint4  g_Qc[(size_t)NL*QN*SS*ROWB/16];   // 28.3 MB fp16 (query)
__device__ uint4  g_Kc[(size_t)NL*KN*SS*ROWB/16];   // 28.3 MB fp16 (key)
__device__ float g_G [NL * SS * SS];
__device__ float g_X [NL * NP * 2 * SS];
__device__ float g_Z [NL * NP * 2];

// ---------------- packed f32x2 helpers ----------------
__device__ __forceinline__ ull fma2(ull a, ull b, ull c) {
    ull d; asm("fma.rn.f32x2 %0, %1, %2, %3;" : "=l"(d) : "l"(a), "l"(b), "l"(c)); return d;
}
__device__ __forceinline__ ull pack2(float x, float y) {
    ull d; asm("mov.b64 %0, {%1, %2};" : "=l"(d) : "f"(x), "f"(y)); return d;
}
__device__ __forceinline__ void unpack2(ull v, float& x, float& y) {
    asm("mov.b64 {%0, %1}, %2;" : "=f"(x), "=f"(y) : "l"(v));
}
__device__ __forceinline__ uint32_t smem_u32(const void* p) {
    uint32_t a;
    asm("{ .reg .u64 t; cvta.to.shared.u64 t, %1; cvt.u32.u64 %0, t; }" : "=r"(a) : "l"(p));
    return a;
}
// sign-aware float atomic max
__device__ __forceinline__ void atomicMaxFloat(float* addr, float val) {
    if (val >= 0.0f) atomicMax((int*)addr, __float_as_int(val));
    else             atomicMin((unsigned int*)addr, (unsigned int)__float_as_int(val));
}

// ---------------- mma / ldmatrix wrappers ----------------
__device__ __forceinline__ void mma_fp16(float* d, const uint32_t* a, uint32_t b0, uint32_t b1) {
    asm volatile("mma.sync.aligned.m16n8k16.row.col.f32.f16.f16.f32 "
                 "{%0,%1,%2,%3}, {%4,%5,%6,%7}, {%8,%9}, {%0,%1,%2,%3};"
                 : "+f"(d[0]), "+f"(d[1]), "+f"(d[2]), "+f"(d[3])
                 : "r"(a[0]), "r"(a[1]), "r"(a[2]), "r"(a[3]), "r"(b0), "r"(b1));
}
__device__ __forceinline__ void ldsm_x4(uint32_t* r, uint32_t addr) {
    asm volatile("ldmatrix.sync.aligned.m8n8.x4.shared.b16 {%0,%1,%2,%3}, [%4];"
                 : "=r"(r[0]), "=r"(r[1]), "=r"(r[2]), "=r"(r[3]) : "r"(addr));
}

// ---------------- kernel 1: gate sigmoid + zero Z + init row-max ----------------
__global__ void gate_init_kernel(const float* __restrict__ se) {
    int idx = blockIdx.x * blockDim.x + threadIdx.x;
    if (idx < NL * SS * SS) g_G[idx] = 1.0f / (1.0f + expf(-se[idx]));
    if (idx < NL * NP * 2)  g_Z[idx] = 0.0f;
    if (idx < NL * NP * SS) {
        int pair = idx / SS, off = idx - pair * SS;
        g_X[(size_t)pair * 2 * SS + off] = -3.402823466e38f;
    }
}

// ---------------- kernel 2: projection GEMM -> fp16 ----------------
__global__ void __launch_bounds__(256)
proj_gemm_kernel(const float* __restrict__ A, const float* __restrict__ W,
                 const float* __restrict__ bias, int dst)
{
    const int i = blockIdx.z;
    const int LDA = NL * DH;
    const float* Ab = A + i * DH;
    const float* Wb = W + (size_t)i * DH * DH;
    const float* bb = bias + i * DH;
    char* outBase = (char*)(dst ? g_Kc : g_Qc) + (size_t)(i * QN * SS) * ROWB;
    const int m0 = blockIdx.y * 128, n0 = blockIdx.x * 128;

    __shared__ __align__(16) float As[16 * 132];
    __shared__ __align__(16) float Bs[16 * 132];

    const int tid = threadIdx.x;
    const int tx = tid & 15, ty = tid >> 4;

    ull acc[8][4];
#pragma unroll
    for (int r = 0; r < 8; r++)
#pragma unroll
        for (int j = 0; j < 4; j++) acc[r][j] = 0ull;

    for (int k0 = 0; k0 < DH; k0 += 16) {
#pragma unroll
        for (int l = 0; l < 2; l++) {
            int idx = tid + l * 256;
            int r = idx >> 2, e4 = idx & 3;
            float4 va = *(const float4*)(Ab + (size_t)(m0 + r) * LDA + k0 + e4 * 4);
            float4 vb = *(const float4*)(Wb + (size_t)(n0 + r) * DH  + k0 + e4 * 4);
            int d = e4 * 4;
            As[(d + 0) * 132 + r] = va.x; As[(d + 1) * 132 + r] = va.y;
            As[(d + 2) * 132 + r] = va.z; As[(d + 3) * 132 + r] = va.w;
            Bs[(d + 0) * 132 + r] = vb.x; Bs[(d + 1) * 132 + r] = vb.y;
            Bs[(d + 2) * 132 + r] = vb.z; Bs[(d + 3) * 132 + r] = vb.w;
        }
        __syncthreads();
#pragma unroll
        for (int d = 0; d < 16; d++) {
            const float* ap = As + d * 132 + ty * 8;
            const float* bp = Bs + d * 132 + tx * 8;
            float4 a0 = *(const float4*)ap;
            float4 a1 = *(const float4*)(ap + 4);
            ulonglong2 bq0 = *(const ulonglong2*)bp;
            ulonglong2 bq1 = *(const ulonglong2*)(bp + 4);
            ull b[4] = { bq0.x, bq0.y, bq1.x, bq1.y };
            float a[8] = { a0.x, a0.y, a0.z, a0.w, a1.x, a1.y, a1.z, a1.w };
#pragma unroll
            for (int r = 0; r < 8; r++) {
                ull ad = pack2(a[r], a[r]);
#pragma unroll
                for (int j = 0; j < 4; j++) acc[r][j] = fma2(ad, b[j], acc[r][j]);
            }
        }
        __syncthreads();
    }

    float bv[8];
#pragma unroll
    for (int j = 0; j < 8; j++) bv[j] = bb[n0 + tx * 8 + j];
#pragma unroll
    for (int r = 0; r < 8; r++) {
        int row = m0 + ty * 8 + r;
        float v[8];
        unpack2(acc[r][0], v[0], v[1]); unpack2(acc[r][1], v[2], v[3]);
        unpack2(acc[r][2], v[4], v[5]); unpack2(acc[r][3], v[6], v[7]);
        uint32_t hi[4];
#pragma unroll
        for (int j = 0; j < 4; j++) {
            float a = v[2*j]   + bv[2*j];
            float b = v[2*j+1] + bv[2*j+1];
            __half2 h = __floats2half2_rn(a, b);
            hi[j] = *reinterpret_cast<uint32_t*>(&h);
        }
        uint4 H = { hi[0], hi[1], hi[2], hi[3] };
        *(uint4*)(outBase + (size_t)row * ROWB + (size_t)(n0 + tx * 8) * 2) = H;
    }
}

// ---------------- kernel 3: HMMA score GEMM + gate + dual max-pool ----------------
// 2 CTAs per (q,k,i): each 192 threads / 6 warps computes 192 x 96 (N split).
#define STAGES 3
#define CHUNK_B 128          /* 64 fp16 per row per chunk */
#define NCHUNK 8             /* 1024 B / 128 B */
#define TILE_A 24576         /* A: 192 rows x 128B; B (96 rows) follows */
#define STAGE_BYTES 36864    /* (192 + 96) * 128 */
#define SM_BASE 1024
#define SMEM_TOTAL_SCORE (SM_BASE + STAGES * STAGE_BYTES)   /* 111616 */

__global__ void __launch_bounds__(192, 2)
score_mma_kernel()
{
    extern __shared__ __align__(128) char dsm[];
    const int i = blockIdx.z, q = blockIdx.y;
    const int k = blockIdx.x >> 1;
    const int h = blockIdx.x & 1;          // N half: cols [h*96, h*96+96)
    const int tid = threadIdx.x;
    const int wid = tid >> 5;
    const int lane = tid & 31;
    uint32_t sb = smem_u32(dsm);

    const char* aG = (const char*)g_Qc + (size_t)((i * QN + q) * SS) * ROWB;
    const char* bG = (const char*)g_Kc + (size_t)((i * KN + k) * SS + h * 96) * ROWB;

    // warp tile: 64 rows x 48 cols. 6 warps = 3 (m) x 2 (n).
    const int mw = wid >> 1, nw = wid & 1;
    const int m0 = mw * 64;
    const int n0 = nw * 48;               // local col within the 96-wide half

    uint32_t baseA[4], baseB[3];
#pragma unroll
    for (int mi = 0; mi < 4; mi++) {
        uint32_t row = (uint32_t)(m0 + mi * 16 + (lane & 15));
        uint32_t off = row * 128 + ((lane >> 4) << 4);
        baseA[mi] = off ^ ((off >> 3) & 0x70);
    }
#pragma unroll
    for (int nt = 0; nt < 3; nt++) {
        uint32_t row = (uint32_t)(n0 + nt * 16 + (lane & 7) + ((lane >> 4) << 3));
        uint32_t off = row * 128 + (((lane >> 3) & 1) << 4);
        baseB[nt] = TILE_A + (off ^ ((off >> 3) & 0x70));
    }

    float acc[4][6][4];
#pragma unroll
    for (int mi = 0; mi < 4; mi++)
#pragma unroll
        for (int ni = 0; ni < 6; ni++)
#pragma unroll
            for (int j = 0; j < 4; j++) acc[mi][ni][j] = 0.0f;

    // producer: A (192 rows) + B (96 rows), 64-col chunk, SW128 swizzle
    auto load_stage = [&](int c, int st) {
        uint32_t base = sb + SM_BASE + st * STAGE_BYTES;
#pragma unroll
        for (int l = 0; l < 12; l++) {
            int idx = tid + l * 192;            // 0..2303 16B units
            int isB = idx >= 1536;
            int j2 = isB ? idx - 1536 : idx;
            int r = j2 >> 3, g = j2 & 7;
            uint32_t off = (uint32_t)(r * 128 + g * 16);
            off ^= (off >> 3) & 0x70;
            uint32_t dst = base + (isB ? TILE_A : 0) + off;
            const void* src = (const void*)((isB ? bG : aG) + (size_t)r * ROWB + c * CHUNK_B + g * 16);
            asm volatile("cp.async.cg.shared.global [%0], [%1], 16;" :: "r"(dst), "l"(src) : "memory");
        }
        asm volatile("cp.async.commit_group;" ::: "memory");
    };

    load_stage(0, 0);
    load_stage(1, 1);

    int stc = 0;        // stage holding chunk it
    int stl = 2;        // stage to load chunk it+2 into
    for (int it = 0; it < NCHUNK; it++) {
        if (it == NCHUNK - 1) asm volatile("cp.async.wait_group 0;" ::: "memory");
        else                  asm volatile("cp.async.wait_group 1;" ::: "memory");
        __syncthreads();                      // publish chunk it; all done computing it-1
        if (it + 2 < NCHUNK) load_stage(it + 2, stl);

        uint32_t stage = sb + SM_BASE + stc * STAGE_BYTES;
#pragma unroll
        for (int ks = 0; ks < 4; ks++) {
            uint32_t kx = (uint32_t)(ks << 5);
            uint32_t a[4][4], b[3][4];
#pragma unroll
            for (int mi = 0; mi < 4; mi++) ldsm_x4(a[mi], stage + (baseA[mi] ^ kx));
#pragma unroll
            for (int nt = 0; nt < 3; nt++) ldsm_x4(b[nt], stage + (baseB[nt] ^ kx));
#pragma unroll
            for (int mi = 0; mi < 4; mi++) {
#pragma unroll
                for (int nt = 0; nt < 3; nt++) {
                    mma_fp16(acc[mi][2 * nt],     a[mi], b[nt][0], b[nt][1]);
                    mma_fp16(acc[mi][2 * nt + 1], a[mi], b[nt][2], b[nt][3]);
                }
            }
        }
        if (++stc == STAGES) stc = 0;
        if (++stl == STAGES) stl = 0;
    }

    // ---- epilogue: gate + dual max-pool (score[t][s], gate[s][t]) ----
    const float* gb = g_G + (size_t)i * SS * SS;
    const int g8 = lane >> 2, t4 = lane & 3;
    float rmax[8], cmax[12];
#pragma unroll
    for (int j = 0; j < 8; j++)  rmax[j] = -3.402823466e38f;
#pragma unroll
    for (int j = 0; j < 12; j++) cmax[j] = -3.402823466e38f;

#pragma unroll
    for (int mi = 0; mi < 4; mi++) {
        int r0 = m0 + mi * 16 + g8;
        int r1 = r0 + 8;
#pragma unroll
        for (int ni = 0; ni < 6; ni++) {
            int c0 = h * 96 + n0 + ni * 8 + t4 * 2;   // global s
            int c1 = c0 + 1;
            float v00 = acc[mi][ni][0] * __ldg(gb + (size_t)c0 * SS + r0);
            float v01 = acc[mi][ni][1] * __ldg(gb + (size_t)c1 * SS + r0);
            float v10 = acc[mi][ni][2] * __ldg(gb + (size_t)c0 * SS + r1);
            float v11 = acc[mi][ni][3] * __ldg(gb + (size_t)c1 * SS + r1);
            rmax[mi * 2]     = fmaxf(rmax[mi * 2],     fmaxf(v00, v01));
            rmax[mi * 2 + 1] = fmaxf(rmax[mi * 2 + 1], fmaxf(v10, v11));
            cmax[ni * 2]     = fmaxf(cmax[ni * 2],     fmaxf(v00, v10));
            cmax[ni * 2 + 1] = fmaxf(cmax[ni * 2 + 1], fmaxf(v01, v11));
        }
    }
#pragma unroll
    for (int m = 1; m <= 2; m <<= 1)
#pragma unroll
        for (int j = 0; j < 8; j++)
            rmax[j] = fmaxf(rmax[j], __shfl_xor_sync(0xffffffffu, rmax[j], m));
#pragma unroll
    for (int m = 4; m <= 16; m <<= 1)
#pragma unroll
        for (int j = 0; j < 12; j++)
            cmax[j] = fmaxf(cmax[j], __shfl_xor_sync(0xffffffffu, cmax[j], m));

    float* red1 = (float*)(dsm + SM_BASE);          // [2][192] by nw
    float* red2 = red1 + 2 * SS;                    // [3][96] by mw
    if (t4 == 0) {
#pragma unroll
        for (int j = 0; j < 8; j++)
            red1[nw * SS + m0 + (j >> 1) * 16 + g8 + (j & 1) * 8] = rmax[j];
    }
    if (g8 == 0) {
#pragma unroll
        for (int j = 0; j < 12; j++)
            red2[mw * 96 + n0 + (j >> 1) * 8 + t4 * 2 + (j & 1)] = cmax[j];
    }
    __syncthreads();

    float* xo = g_X + ((size_t)i * NP + (size_t)q * KN + k) * (2 * SS);
    {
        float m = fmaxf(red1[tid], red1[SS + tid]);      // partial over this half's 96 cols
        atomicMaxFloat(&xo[tid], m);
    }
    if (tid < 96) {
        float m = fmaxf(fmaxf(red2[tid], red2[96 + tid]), red2[192 + tid]);
        xo[SS + h * 96 + tid] = m;                       // complete over all 192 rows
    }
}

// ---------------- kernel 4: bn1 -> fc2 -> bn2 -> relu -> fc3 row-reduce ----------------
__global__ void __launch_bounds__(256)
mlp_kernel(const float* __restrict__ w2, const float* __restrict__ b2,
           const float* __restrict__ g2, const float* __restrict__ bb2,
           const float* __restrict__ w3,
           const float* __restrict__ g1, const float* __restrict__ bb1)
{
    const int i = blockIdx.z;
    const int row0 = blockIdx.y * 64;
    const int col0 = blockIdx.x * 128;
    const float scale = 1.0f / sqrtf(1.0f + 1e-5f);
    const float g1c = g1[i] * scale, b1v = bb1[i];
    const float* Xb  = g_X + (size_t)i * NP * 2 * SS;
    const float* W2b = w2  + (size_t)i * DFFN * SS;

    __shared__ __align__(16) float As[16 * 68];
    __shared__ __align__(16) float Bs[16 * 132];
    __shared__ float zsh[64];

    const int tid = threadIdx.x;
    const int tx = tid & 15, ty = tid >> 4;
    if (tid < 64) zsh[tid] = 0.0f;

    ull acc[4][4];
#pragma unroll
    for (int r = 0; r < 4; r++)
#pragma unroll
        for (int j = 0; j < 4; j++) acc[r][j] = 0ull;

    for (int k0 = 0; k0 < SS; k0 += 16) {
        {
            int r = tid >> 2, e4 = tid & 3;
            float4 va = *(const float4*)(Xb + (size_t)(row0 + r) * SS + k0 + e4 * 4);
            va.x = va.x * g1c + b1v; va.y = va.y * g1c + b1v;
            va.z = va.z * g1c + b1v; va.w = va.w * g1c + b1v;
            int d = e4 * 4;
            As[(d + 0) * 68 + r] = va.x; As[(d + 1) * 68 + r] = va.y;
            As[(d + 2) * 68 + r] = va.z; As[(d + 3) * 68 + r] = va.w;
        }
#pragma unroll
        for (int l = 0; l < 2; l++) {
            int idx = tid + l * 256;
            int c = idx >> 2, e4 = idx & 3;
            float4 vb = *(const float4*)(W2b + (size_t)(col0 + c) * SS + k0 + e4 * 4);
            int d = e4 * 4;
            Bs[(d + 0) * 132 + c] = vb.x; Bs[(d + 1) * 132 + c] = vb.y;
            Bs[(d + 2) * 132 + c] = vb.z; Bs[(d + 3) * 132 + c] = vb.w;
        }
        __syncthreads();
#pragma unroll
        for (int d = 0; d < 16; d++) {
            const float* ap = As + d * 68 + ty * 4;
            const float* bp = Bs + d * 132 + tx * 8;
            float4 a0 = *(const float4*)ap;
            ulonglong2 bq0 = *(const ulonglong2*)bp;
            ulonglong2 bq1 = *(const ulonglong2*)(bp + 4);
            ull b[4] = { bq0.x, bq0.y, bq1.x, bq1.y };
            float a[4] = { a0.x, a0.y, a0.z, a0.w };
#pragma unroll
            for (int r = 0; r < 4; r++) {
                ull ad = pack2(a[r], a[r]);
#pragma unroll
                for (int j = 0; j < 4; j++) acc[r][j] = fma2(ad, b[j], acc[r][j]);
            }
        }
        __syncthreads();
    }

    const int cb = col0 + tx * 8;
    float b2v[8], g2v[8], bb2v[8], w3v[8];
    {
        const float4* p;
        p = (const float4*)(b2  + (size_t)i * DFFN + cb);
        float4 u0 = p[0], u1 = p[1];
        b2v[0]=u0.x; b2v[1]=u0.y; b2v[2]=u0.z; b2v[3]=u0.w;
        b2v[4]=u1.x; b2v[5]=u1.y; b2v[6]=u1.z; b2v[7]=u1.w;
        p = (const float4*)(g2  + (size_t)i * DFFN + cb);
        u0 = p[0]; u1 = p[1];
        g2v[0]=u0.x; g2v[1]=u0.y; g2v[2]=u0.z; g2v[3]=u0.w;
        g2v[4]=u1.x; g2v[5]=u1.y; g2v[6]=u1.z; g2v[7]=u1.w;
        p = (const float4*)(bb2 + (size_t)i * DFFN + cb);
        u0 = p[0]; u1 = p[1];
        bb2v[0]=u0.x; bb2v[1]=u0.y; bb2v[2]=u0.z; bb2v[3]=u0.w;
        bb2v[4]=u1.x; bb2v[5]=u1.y; bb2v[6]=u1.z; bb2v[7]=u1.w;
        p = (const float4*)(w3  + (size_t)i * DFFN + cb);
        u0 = p[0]; u1 = p[1];
        w3v[0]=u0.x; w3v[1]=u0.y; w3v[2]=u0.z; w3v[3]=u0.w;
        w3v[4]=u1.x; w3v[5]=u1.y; w3v[6]=u1.z; w3v[7]=u1.w;
    }

#pragma unroll
    for (int r = 0; r < 4; r++) {
        float zp = 0.0f;
#pragma unroll
        for (int j = 0; j < 4; j++) {
            float y0, y1;
            unpack2(acc[r][j], y0, y1);
            y0 += b2v[2 * j];     y1 += b2v[2 * j + 1];
            float yb0 = y0 * (g2v[2 * j] * scale)     + bb2v[2 * j];
            float yb1 = y1 * (g2v[2 * j + 1] * scale) + bb2v[2 * j + 1];
            if (yb0 > 0.0f) zp += yb0 * w3v[2 * j];
            if (yb1 > 0.0f) zp += yb1 * w3v[2 * j + 1];
        }
        atomicAdd(&zsh[ty * 4 + r], zp);
    }
    __syncthreads();
    if (tid < 64) atomicAdd(&g_Z[(size_t)i * NP * 2 + row0 + tid], zsh[tid]);
}

// ---------------- kernel 5: pair-sum, bn3, layer-sum, decoder norm ----------------
__global__ void final_kernel(const float* __restrict__ fc3_b,
                             const float* __restrict__ bn3_g, const float* __restrict__ bn3_b,
                             const float* __restrict__ norm_g, const float* __restrict__ norm_b,
                             float* __restrict__ out)
{
    int p = blockIdx.x * blockDim.x + threadIdx.x;
    if (p >= NP) return;
    const float scale = 1.0f / sqrtf(1.0f + 1e-5f);
    float acc = 0.0f;
#pragma unroll
    for (int i = 0; i < NL; i++) {
        float u = g_Z[i * NP * 2 + 2 * p] + g_Z[i * NP * 2 + 2 * p + 1] + 2.0f * fc3_b[i];
        acc += u * (bn3_g[i] * scale) + bn3_b[i];
    }
    out[p] = acc * (norm_g[0] * scale) + norm_b[0];
}

// ---------------- launch ----------------
extern "C" void kernel_launch(void* const* d_in, const int* in_sizes, int n_in,
                              void* d_out, int out_size)
{
    (void)in_sizes; (void)n_in; (void)out_size;
    const float* memory_  = (const float*)d_in[0];
    const float* features = (const float*)d_in[1];
    const float* fc1_w  = (const float*)d_in[2];
    const float* fc1_b  = (const float*)d_in[3];
    const float* se     = (const float*)d_in[4];
    const float* bn1_g  = (const float*)d_in[5];
    const float* bn1_b  = (const float*)d_in[6];
    const float* fc2_w  = (const float*)d_in[7];
    const float* fc2_b  = (const float*)d_in[8];
    const float* bn2_g  = (const float*)d_in[9];
    const float* bn2_b  = (const float*)d_in[10];
    const float* fc3_w  = (const float*)d_in[11];
    const float* fc3_b  = (const float*)d_in[12];
    const float* bn3_g  = (const float*)d_in[13];
    const float* bn3_b  = (const float*)d_in[14];
    const float* norm_g = (const float*)d_in[15];
    const float* norm_b = (const float*)d_in[16];
    float* out = (float*)d_out;

    cudaFuncSetAttribute(score_mma_kernel,
                         cudaFuncAttributeMaxDynamicSharedMemorySize, SMEM_TOTAL_SCORE);

    gate_init_kernel<<<(NL * NP * SS + 255) / 256, 256>>>(se);

    dim3 gproj(DH / 128, (QN * SS) / 128, NL);
    proj_gemm_kernel<<<gproj, 256>>>(memory_,  fc1_w, fc1_b, 0);
    proj_gemm_kernel<<<gproj, 256>>>(features, fc1_w, fc1_b, 1);

    score_mma_kernel<<<dim3(KN * 2, QN, NL), 192, SMEM_TOTAL_SCORE>>>();

    mlp_kernel<<<dim3(DFFN / 128, (2 * NP) / 64, NL), 256>>>(
        fc2_w, fc2_b, bn2_g, bn2_b, fc3_w, bn1_g, bn1_b);

    final_kernel<<<(NP + 255) / 256, 256>>>(fc3_b, bn3_g, bn3_b, norm_g, norm_b, out);
}

// round 9
// speedup vs baseline: 1.8045x; 1.0769x over previous
#include <cuda_runtime.h>
#include <cuda_bf16.h>
#include <cuda_fp16.h>
#include <math.h>
#include <stdint.h>

typedef unsigned long long ull;

#define QN 48
#define KN 48
#define SS 192
#define DH 512
#define NL 3
#define DFFN 2048
#define NP (QN*KN)   /* 2304 */
#define KC 512       /* single fp16: K = D */
#define ROWB 1024    /* bytes per row = KC * 2 */

// ---------------- scratch (device globals) ----------------
__device__ uint4  g_Qc[(size_t)NL*QN*SS*ROWB/16];   // 28.3 MB fp16 (query)
__device__ uint4  g_Kc[(size_t)NL*KN*SS*ROWB/16];   // 28.3 MB fp16 (key)
__device__ float g_G [NL * SS * SS];
__device__ float g_X [NL * NP * 2 * SS];
__device__ float g_Z [NL * NP * 2];

// ---------------- packed f32x2 helpers (used by mlp) ----------------
__device__ __forceinline__ ull fma2(ull a, ull b, ull c) {
    ull d; asm("fma.rn.f32x2 %0, %1, %2, %3;" : "=l"(d) : "l"(a), "l"(b), "l"(c)); return d;
}
__device__ __forceinline__ ull pack2(float x, float y) {
    ull d; asm("mov.b64 %0, {%1, %2};" : "=l"(d) : "f"(x), "f"(y)); return d;
}
__device__ __forceinline__ void unpack2(ull v, float& x, float& y) {
    asm("mov.b64 {%0, %1}, %2;" : "=f"(x), "=f"(y) : "l"(v));
}
__device__ __forceinline__ uint32_t smem_u32(const void* p) {
    uint32_t a;
    asm("{ .reg .u64 t; cvta.to.shared.u64 t, %1; cvt.u32.u64 %0, t; }" : "=r"(a) : "l"(p));
    return a;
}
// sign-aware float atomic max
__device__ __forceinline__ void atomicMaxFloat(float* addr, float val) {
    if (val >= 0.0f) atomicMax((int*)addr, __float_as_int(val));
    else             atomicMin((unsigned int*)addr, (unsigned int)__float_as_int(val));
}

// ---------------- mma / ldmatrix wrappers ----------------
__device__ __forceinline__ void mma_fp16(float* d, const uint32_t* a, uint32_t b0, uint32_t b1) {
    asm volatile("mma.sync.aligned.m16n8k16.row.col.f32.f16.f16.f32 "
                 "{%0,%1,%2,%3}, {%4,%5,%6,%7}, {%8,%9}, {%0,%1,%2,%3};"
                 : "+f"(d[0]), "+f"(d[1]), "+f"(d[2]), "+f"(d[3])
                 : "r"(a[0]), "r"(a[1]), "r"(a[2]), "r"(a[3]), "r"(b0), "r"(b1));
}
__device__ __forceinline__ void ldsm_x4(uint32_t* r, uint32_t addr) {
    asm volatile("ldmatrix.sync.aligned.m8n8.x4.shared.b16 {%0,%1,%2,%3}, [%4];"
                 : "=r"(r[0]), "=r"(r[1]), "=r"(r[2]), "=r"(r[3]) : "r"(addr));
}

// ---------------- kernel 1: gate sigmoid + zero Z + init row-max ----------------
__global__ void gate_init_kernel(const float* __restrict__ se) {
    int idx = blockIdx.x * blockDim.x + threadIdx.x;
    if (idx < NL * SS * SS) g_G[idx] = 1.0f / (1.0f + expf(-se[idx]));
    if (idx < NL * NP * 2)  g_Z[idx] = 0.0f;
    if (idx < NL * NP * SS) {
        int pair = idx / SS, off = idx - pair * SS;
        g_X[(size_t)pair * 2 * SS + off] = -3.402823466e38f;
    }
}

// ---------------- kernel 2: projection GEMM (HMMA, split-fp16 activations) ----------------
// C[m][n] = A[m][:].W[n][:] + b[n]; A split [ah|al] (K=1024 virtual), W rounded once.
#define PCH 16        /* virtual 64-half chunks: 1024/64 */
#define PSTG 32768    /* stage: A 16K + W 16K */

__global__ void __launch_bounds__(256)
proj_mma_kernel(const float* __restrict__ A, const float* __restrict__ W,
                const float* __restrict__ bias, int dst)
{
    extern __shared__ __align__(128) char psm[];
    const int i = blockIdx.z;
    const int LDA = NL * DH;
    const float* Ab = A + i * DH;
    const float* Wb = W + (size_t)i * DH * DH;
    const float* bb = bias + i * DH;
    char* outBase = (char*)(dst ? g_Kc : g_Qc) + (size_t)(i * QN * SS) * ROWB;
    const int m0 = blockIdx.y * 128, n0 = blockIdx.x * 128;
    const int tid = threadIdx.x, wid = tid >> 5, lane = tid & 31;
    uint32_t sb = smem_u32(psm);
    const int mw = wid >> 2, nw = wid & 3;      // 2 (m) x 4 (n)
    const int m0w = mw * 64, n0w = nw * 32;

    uint32_t baseA[4], baseB[2];
#pragma unroll
    for (int mi = 0; mi < 4; mi++) {
        uint32_t row = (uint32_t)(m0w + mi * 16 + (lane & 15));
        uint32_t off = row * 128 + ((lane >> 4) << 4);
        baseA[mi] = off ^ ((off >> 3) & 0x70);
    }
#pragma unroll
    for (int nj = 0; nj < 2; nj++) {
        uint32_t row = (uint32_t)(n0w + nj * 16 + (lane & 7) + ((lane >> 4) << 3));
        uint32_t off = row * 128 + (((lane >> 3) & 1) << 4);
        baseB[nj] = 16384u + (off ^ ((off >> 3) & 0x70));
    }

    float acc[4][4][4];
#pragma unroll
    for (int mi = 0; mi < 4; mi++)
#pragma unroll
        for (int n8 = 0; n8 < 4; n8++)
#pragma unroll
            for (int j = 0; j < 4; j++) acc[mi][n8][j] = 0.0f;

    uint4 stg[8];

    auto load_chunk = [&](int c) {
        const int co0 = (c & 7) * 64;
        const bool lo = (c >= 8);
#pragma unroll
        for (int u = 0; u < 8; u++) {
            int idx = tid + u * 256;
            int isW = idx >= 1024;
            int j = idx & 1023;
            int r = j >> 3, g = j & 7;
            const float* src = isW ? (Wb + (size_t)(n0 + r) * DH  + co0 + g * 8)
                                   : (Ab + (size_t)(m0 + r) * LDA + co0 + g * 8);
            float4 f0 = *(const float4*)src;
            float4 f1 = *(const float4*)(src + 4);
            uint32_t h[4];
            if (!lo || isW) {
                __half2 a0 = __floats2half2_rn(f0.x, f0.y);
                __half2 a1 = __floats2half2_rn(f0.z, f0.w);
                __half2 a2 = __floats2half2_rn(f1.x, f1.y);
                __half2 a3 = __floats2half2_rn(f1.z, f1.w);
                h[0] = *reinterpret_cast<uint32_t*>(&a0);
                h[1] = *reinterpret_cast<uint32_t*>(&a1);
                h[2] = *reinterpret_cast<uint32_t*>(&a2);
                h[3] = *reinterpret_cast<uint32_t*>(&a3);
            } else {
                __half2 a0 = __floats2half2_rn(f0.x, f0.y);
                __half2 a1 = __floats2half2_rn(f0.z, f0.w);
                __half2 a2 = __floats2half2_rn(f1.x, f1.y);
                __half2 a3 = __floats2half2_rn(f1.z, f1.w);
                float2 r0 = __half22float2(a0), r1 = __half22float2(a1);
                float2 r2 = __half22float2(a2), r3 = __half22float2(a3);
                __half2 l0 = __floats2half2_rn(f0.x - r0.x, f0.y - r0.y);
                __half2 l1 = __floats2half2_rn(f0.z - r1.x, f0.w - r1.y);
                __half2 l2 = __floats2half2_rn(f1.x - r2.x, f1.y - r2.y);
                __half2 l3 = __floats2half2_rn(f1.z - r3.x, f1.w - r3.y);
                h[0] = *reinterpret_cast<uint32_t*>(&l0);
                h[1] = *reinterpret_cast<uint32_t*>(&l1);
                h[2] = *reinterpret_cast<uint32_t*>(&l2);
                h[3] = *reinterpret_cast<uint32_t*>(&l3);
            }
            stg[u].x = h[0]; stg[u].y = h[1]; stg[u].z = h[2]; stg[u].w = h[3];
        }
    };
    auto store_chunk = [&](int buf) {
#pragma unroll
        for (int u = 0; u < 8; u++) {
            int idx = tid + u * 256;
            int isW = idx >= 1024;
            int j = idx & 1023;
            int r = j >> 3, g = j & 7;
            uint32_t off = (uint32_t)(r * 128 + g * 16);
            off ^= (off >> 3) & 0x70;
            *(uint4*)(psm + buf * PSTG + (isW ? 16384 : 0) + off) = stg[u];
        }
    };

    load_chunk(0);
    int buf = 0;
    for (int c = 0; c < PCH; c++) {
        store_chunk(buf);
        __syncthreads();
        if (c + 1 < PCH) load_chunk(c + 1);

        uint32_t stage = sb + buf * PSTG;
#pragma unroll
        for (int ks = 0; ks < 4; ks++) {
            uint32_t kx = (uint32_t)(ks << 5);
            uint32_t a[4][4], b[2][4];
#pragma unroll
            for (int mi = 0; mi < 4; mi++) ldsm_x4(a[mi], stage + (baseA[mi] ^ kx));
#pragma unroll
            for (int nj = 0; nj < 2; nj++) ldsm_x4(b[nj], stage + (baseB[nj] ^ kx));
#pragma unroll
            for (int mi = 0; mi < 4; mi++)
#pragma unroll
                for (int n8 = 0; n8 < 4; n8++)
                    mma_fp16(acc[mi][n8], a[mi], b[n8 >> 1][(n8 & 1) * 2], b[n8 >> 1][(n8 & 1) * 2 + 1]);
        }
        buf ^= 1;
    }

    // epilogue: + bias, round to fp16, store half2
    const int g8 = lane >> 2, t4 = lane & 3;
    float bv[8];
#pragma unroll
    for (int n8 = 0; n8 < 4; n8++) {
        bv[n8 * 2]     = bb[n0 + n0w + n8 * 8 + t4 * 2];
        bv[n8 * 2 + 1] = bb[n0 + n0w + n8 * 8 + t4 * 2 + 1];
    }
#pragma unroll
    for (int mi = 0; mi < 4; mi++) {
        int r0 = m0 + m0w + mi * 16 + g8;
#pragma unroll
        for (int n8 = 0; n8 < 4; n8++) {
            int c0 = n0 + n0w + n8 * 8 + t4 * 2;
            __half2 v0 = __floats2half2_rn(acc[mi][n8][0] + bv[n8 * 2], acc[mi][n8][1] + bv[n8 * 2 + 1]);
            __half2 v1 = __floats2half2_rn(acc[mi][n8][2] + bv[n8 * 2], acc[mi][n8][3] + bv[n8 * 2 + 1]);
            *(__half2*)(outBase + (size_t)r0 * ROWB + c0 * 2)       = v0;
            *(__half2*)(outBase + (size_t)(r0 + 8) * ROWB + c0 * 2) = v1;
        }
    }
}

// ---------------- kernel 3: HMMA score GEMM + gate + dual max-pool ----------------
// 2 CTAs per (q,k,i): each 192 threads / 6 warps computes 192 x 96 (N split).
#define STAGES 3
#define CHUNK_B 128          /* 64 fp16 per row per chunk */
#define NCHUNK 8             /* 1024 B / 128 B */
#define TILE_A 24576         /* A: 192 rows x 128B; B (96 rows) follows */
#define STAGE_BYTES 36864    /* (192 + 96) * 128 */
#define SM_BASE 1024
#define SMEM_TOTAL_SCORE (SM_BASE + STAGES * STAGE_BYTES)   /* 111616 */

__global__ void __launch_bounds__(192, 2)
score_mma_kernel()
{
    extern __shared__ __align__(128) char dsm[];
    const int i = blockIdx.z, q = blockIdx.y;
    const int k = blockIdx.x >> 1;
    const int h = blockIdx.x & 1;          // N half: cols [h*96, h*96+96)
    const int tid = threadIdx.x;
    const int wid = tid >> 5;
    const int lane = tid & 31;
    uint32_t sb = smem_u32(dsm);

    const char* aG = (const char*)g_Qc + (size_t)((i * QN + q) * SS) * ROWB;
    const char* bG = (const char*)g_Kc + (size_t)((i * KN + k) * SS + h * 96) * ROWB;

    // warp tile: 64 rows x 48 cols. 6 warps = 3 (m) x 2 (n).
    const int mw = wid >> 1, nw = wid & 1;
    const int m0 = mw * 64;
    const int n0 = nw * 48;               // local col within the 96-wide half

    uint32_t baseA[4], baseB[3];
#pragma unroll
    for (int mi = 0; mi < 4; mi++) {
        uint32_t row = (uint32_t)(m0 + mi * 16 + (lane & 15));
        uint32_t off = row * 128 + ((lane >> 4) << 4);
        baseA[mi] = off ^ ((off >> 3) & 0x70);
    }
#pragma unroll
    for (int nt = 0; nt < 3; nt++) {
        uint32_t row = (uint32_t)(n0 + nt * 16 + (lane & 7) + ((lane >> 4) << 3));
        uint32_t off = row * 128 + (((lane >> 3) & 1) << 4);
        baseB[nt] = TILE_A + (off ^ ((off >> 3) & 0x70));
    }

    float acc[4][6][4];
#pragma unroll
    for (int mi = 0; mi < 4; mi++)
#pragma unroll
        for (int ni = 0; ni < 6; ni++)
#pragma unroll
            for (int j = 0; j < 4; j++) acc[mi][ni][j] = 0.0f;

    // producer: A (192 rows) + B (96 rows), 64-col chunk, SW128 swizzle
    auto load_stage = [&](int c, int st) {
        uint32_t base = sb + SM_BASE + st * STAGE_BYTES;
#pragma unroll
        for (int l = 0; l < 12; l++) {
            int idx = tid + l * 192;            // 0..2303 16B units
            int isB = idx >= 1536;
            int j2 = isB ? idx - 1536 : idx;
            int r = j2 >> 3, g = j2 & 7;
            uint32_t off = (uint32_t)(r * 128 + g * 16);
            off ^= (off >> 3) & 0x70;
            uint32_t dst = base + (isB ? TILE_A : 0) + off;
            const void* src = (const void*)((isB ? bG : aG) + (size_t)r * ROWB + c * CHUNK_B + g * 16);
            asm volatile("cp.async.cg.shared.global [%0], [%1], 16;" :: "r"(dst), "l"(src) : "memory");
        }
        asm volatile("cp.async.commit_group;" ::: "memory");
    };

    load_stage(0, 0);
    load_stage(1, 1);

    int stc = 0;        // stage holding chunk it
    int stl = 2;        // stage to load chunk it+2 into
    for (int it = 0; it < NCHUNK; it++) {
        if (it == NCHUNK - 1) asm volatile("cp.async.wait_group 0;" ::: "memory");
        else                  asm volatile("cp.async.wait_group 1;" ::: "memory");
        __syncthreads();                      // publish chunk it; all done computing it-1
        if (it + 2 < NCHUNK) load_stage(it + 2, stl);

        uint32_t stage = sb + SM_BASE + stc * STAGE_BYTES;
#pragma unroll
        for (int ks = 0; ks < 4; ks++) {
            uint32_t kx = (uint32_t)(ks << 5);
            uint32_t a[4][4], b[3][4];
#pragma unroll
            for (int mi = 0; mi < 4; mi++) ldsm_x4(a[mi], stage + (baseA[mi] ^ kx));
#pragma unroll
            for (int nt = 0; nt < 3; nt++) ldsm_x4(b[nt], stage + (baseB[nt] ^ kx));
#pragma unroll
            for (int mi = 0; mi < 4; mi++) {
#pragma unroll
                for (int nt = 0; nt < 3; nt++) {
                    mma_fp16(acc[mi][2 * nt],     a[mi], b[nt][0], b[nt][1]);
                    mma_fp16(acc[mi][2 * nt + 1], a[mi], b[nt][2], b[nt][3]);
                }
            }
        }
        if (++stc == STAGES) stc = 0;
        if (++stl == STAGES) stl = 0;
    }

    // ---- epilogue: gate + dual max-pool (score[t][s], gate[s][t]) ----
    const float* gb = g_G + (size_t)i * SS * SS;
    const int g8 = lane >> 2, t4 = lane & 3;
    float rmax[8], cmax[12];
#pragma unroll
    for (int j = 0; j < 8; j++)  rmax[j] = -3.402823466e38f;
#pragma unroll
    for (int j = 0; j < 12; j++) cmax[j] = -3.402823466e38f;

#pragma unroll
    for (int mi = 0; mi < 4; mi++) {
        int r0 = m0 + mi * 16 + g8;
        int r1 = r0 + 8;
#pragma unroll
        for (int ni = 0; ni < 6; ni++) {
            int c0 = h * 96 + n0 + ni * 8 + t4 * 2;   // global s
            int c1 = c0 + 1;
            float v00 = acc[mi][ni][0] * __ldg(gb + (size_t)c0 * SS + r0);
            float v01 = acc[mi][ni][1] * __ldg(gb + (size_t)c1 * SS + r0);
            float v10 = acc[mi][ni][2] * __ldg(gb + (size_t)c0 * SS + r1);
            float v11 = acc[mi][ni][3] * __ldg(gb + (size_t)c1 * SS + r1);
            rmax[mi * 2]     = fmaxf(rmax[mi * 2],     fmaxf(v00, v01));
            rmax[mi * 2 + 1] = fmaxf(rmax[mi * 2 + 1], fmaxf(v10, v11));
            cmax[ni * 2]     = fmaxf(cmax[ni * 2],     fmaxf(v00, v10));
            cmax[ni * 2 + 1] = fmaxf(cmax[ni * 2 + 1], fmaxf(v01, v11));
        }
    }
#pragma unroll
    for (int m = 1; m <= 2; m <<= 1)
#pragma unroll
        for (int j = 0; j < 8; j++)
            rmax[j] = fmaxf(rmax[j], __shfl_xor_sync(0xffffffffu, rmax[j], m));
#pragma unroll
    for (int m = 4; m <= 16; m <<= 1)
#pragma unroll
        for (int j = 0; j < 12; j++)
            cmax[j] = fmaxf(cmax[j], __shfl_xor_sync(0xffffffffu, cmax[j], m));

    float* red1 = (float*)(dsm + SM_BASE);          // [2][192] by nw
    float* red2 = red1 + 2 * SS;                    // [3][96] by mw
    if (t4 == 0) {
#pragma unroll
        for (int j = 0; j < 8; j++)
            red1[nw * SS + m0 + (j >> 1) * 16 + g8 + (j & 1) * 8] = rmax[j];
    }
    if (g8 == 0) {
#pragma unroll
        for (int j = 0; j < 12; j++)
            red2[mw * 96 + n0 + (j >> 1) * 8 + t4 * 2 + (j & 1)] = cmax[j];
    }
    __syncthreads();

    float* xo = g_X + ((size_t)i * NP + (size_t)q * KN + k) * (2 * SS);
    {
        float m = fmaxf(red1[tid], red1[SS + tid]);      // partial over this half's 96 cols
        atomicMaxFloat(&xo[tid], m);
    }
    if (tid < 96) {
        float m = fmaxf(fmaxf(red2[tid], red2[96 + tid]), red2[192 + tid]);
        xo[SS + h * 96 + tid] = m;                       // complete over all 192 rows
    }
}

// ---------------- kernel 4: bn1 -> fc2 -> bn2 -> relu -> fc3 row-reduce ----------------
__global__ void __launch_bounds__(256)
mlp_kernel(const float* __restrict__ w2, const float* __restrict__ b2,
           const float* __restrict__ g2, const float* __restrict__ bb2,
           const float* __restrict__ w3,
           const float* __restrict__ g1, const float* __restrict__ bb1)
{
    const int i = blockIdx.z;
    const int row0 = blockIdx.y * 64;
    const int col0 = blockIdx.x * 128;
    const float scale = 1.0f / sqrtf(1.0f + 1e-5f);
    const float g1c = g1[i] * scale, b1v = bb1[i];
    const float* Xb  = g_X + (size_t)i * NP * 2 * SS;
    const float* W2b = w2  + (size_t)i * DFFN * SS;

    __shared__ __align__(16) float As[16 * 68];
    __shared__ __align__(16) float Bs[16 * 132];
    __shared__ float zsh[64];

    const int tid = threadIdx.x;
    const int tx = tid & 15, ty = tid >> 4;
    if (tid < 64) zsh[tid] = 0.0f;

    ull acc[4][4];
#pragma unroll
    for (int r = 0; r < 4; r++)
#pragma unroll
        for (int j = 0; j < 4; j++) acc[r][j] = 0ull;

    for (int k0 = 0; k0 < SS; k0 += 16) {
        {
            int r = tid >> 2, e4 = tid & 3;
            float4 va = *(const float4*)(Xb + (size_t)(row0 + r) * SS + k0 + e4 * 4);
            va.x = va.x * g1c + b1v; va.y = va.y * g1c + b1v;
            va.z = va.z * g1c + b1v; va.w = va.w * g1c + b1v;
            int d = e4 * 4;
            As[(d + 0) * 68 + r] = va.x; As[(d + 1) * 68 + r] = va.y;
            As[(d + 2) * 68 + r] = va.z; As[(d + 3) * 68 + r] = va.w;
        }
#pragma unroll
        for (int l = 0; l < 2; l++) {
            int idx = tid + l * 256;
            int c = idx >> 2, e4 = idx & 3;
            float4 vb = *(const float4*)(W2b + (size_t)(col0 + c) * SS + k0 + e4 * 4);
            int d = e4 * 4;
            Bs[(d + 0) * 132 + c] = vb.x; Bs[(d + 1) * 132 + c] = vb.y;
            Bs[(d + 2) * 132 + c] = vb.z; Bs[(d + 3) * 132 + c] = vb.w;
        }
        __syncthreads();
#pragma unroll
        for (int d = 0; d < 16; d++) {
            const float* ap = As + d * 68 + ty * 4;
            const float* bp = Bs + d * 132 + tx * 8;
            float4 a0 = *(const float4*)ap;
            ulonglong2 bq0 = *(const ulonglong2*)bp;
            ulonglong2 bq1 = *(const ulonglong2*)(bp + 4);
            ull b[4] = { bq0.x, bq0.y, bq1.x, bq1.y };
            float a[4] = { a0.x, a0.y, a0.z, a0.w };
#pragma unroll
            for (int r = 0; r < 4; r++) {
                ull ad = pack2(a[r], a[r]);
#pragma unroll
                for (int j = 0; j < 4; j++) acc[r][j] = fma2(ad, b[j], acc[r][j]);
            }
        }
        __syncthreads();
    }

    const int cb = col0 + tx * 8;
    float b2v[8], g2v[8], bb2v[8], w3v[8];
    {
        const float4* p;
        p = (const float4*)(b2  + (size_t)i * DFFN + cb);
        float4 u0 = p[0], u1 = p[1];
        b2v[0]=u0.x; b2v[1]=u0.y; b2v[2]=u0.z; b2v[3]=u0.w;
        b2v[4]=u1.x; b2v[5]=u1.y; b2v[6]=u1.z; b2v[7]=u1.w;
        p = (const float4*)(g2  + (size_t)i * DFFN + cb);
        u0 = p[0]; u1 = p[1];
        g2v[0]=u0.x; g2v[1]=u0.y; g2v[2]=u0.z; g2v[3]=u0.w;
        g2v[4]=u1.x; g2v[5]=u1.y; g2v[6]=u1.z; g2v[7]=u1.w;
        p = (const float4*)(bb2 + (size_t)i * DFFN + cb);
        u0 = p[0]; u1 = p[1];
        bb2v[0]=u0.x; bb2v[1]=u0.y; bb2v[2]=u0.z; bb2v[3]=u0.w;
        bb2v[4]=u1.x; bb2v[5]=u1.y; bb2v[6]=u1.z; bb2v[7]=u1.w;
        p = (const float4*)(w3  + (size_t)i * DFFN + cb);
        u0 = p[0]; u1 = p[1];
        w3v[0]=u0.x; w3v[1]=u0.y; w3v[2]=u0.z; w3v[3]=u0.w;
        w3v[4]=u1.x; w3v[5]=u1.y; w3v[6]=u1.z; w3v[7]=u1.w;
    }

#pragma unroll
    for (int r = 0; r < 4; r++) {
        float zp = 0.0f;
#pragma unroll
        for (int j = 0; j < 4; j++) {
            float y0, y1;
            unpack2(acc[r][j], y0, y1);
            y0 += b2v[2 * j];     y1 += b2v[2 * j + 1];
            float yb0 = y0 * (g2v[2 * j] * scale)     + bb2v[2 * j];
            float yb1 = y1 * (g2v[2 * j + 1] * scale) + bb2v[2 * j + 1];
            if (yb0 > 0.0f) zp += yb0 * w3v[2 * j];
            if (yb1 > 0.0f) zp += yb1 * w3v[2 * j + 1];
        }
        atomicAdd(&zsh[ty * 4 + r], zp);
    }
    __syncthreads();
    if (tid < 64) atomicAdd(&g_Z[(size_t)i * NP * 2 + row0 + tid], zsh[tid]);
}

// ---------------- kernel 5: pair-sum, bn3, layer-sum, decoder norm ----------------
__global__ void final_kernel(const float* __restrict__ fc3_b,
                             const float* __restrict__ bn3_g, const float* __restrict__ bn3_b,
                             const float* __restrict__ norm_g, const float* __restrict__ norm_b,
                             float* __restrict__ out)
{
    int p = blockIdx.x * blockDim.x + threadIdx.x;
    if (p >= NP) return;
    const float scale = 1.0f / sqrtf(1.0f + 1e-5f);
    float acc = 0.0f;
#pragma unroll
    for (int i = 0; i < NL; i++) {
        float u = g_Z[i * NP * 2 + 2 * p] + g_Z[i * NP * 2 + 2 * p + 1] + 2.0f * fc3_b[i];
        acc += u * (bn3_g[i] * scale) + bn3_b[i];
    }
    out[p] = acc * (norm_g[0] * scale) + norm_b[0];
}

// ---------------- launch ----------------
extern "C" void kernel_launch(void* const* d_in, const int* in_sizes, int n_in,
                              void* d_out, int out_size)
{
    (void)in_sizes; (void)n_in; (void)out_size;
    const float* memory_  = (const float*)d_in[0];
    const float* features = (const float*)d_in[1];
    const float* fc1_w  = (const float*)d_in[2];
    const float* fc1_b  = (const float*)d_in[3];
    const float* se     = (const float*)d_in[4];
    const float* bn1_g  = (const float*)d_in[5];
    const float* bn1_b  = (const float*)d_in[6];
    const float* fc2_w  = (const float*)d_in[7];
    const float* fc2_b  = (const float*)d_in[8];
    const float* bn2_g  = (const float*)d_in[9];
    const float* bn2_b  = (const float*)d_in[10];
    const float* fc3_w  = (const float*)d_in[11];
    const float* fc3_b  = (const float*)d_in[12];
    const float* bn3_g  = (const float*)d_in[13];
    const float* bn3_b  = (const float*)d_in[14];
    const float* norm_g = (const float*)d_in[15];
    const float* norm_b = (const float*)d_in[16];
    float* out = (float*)d_out;

    cudaFuncSetAttribute(score_mma_kernel,
                         cudaFuncAttributeMaxDynamicSharedMemorySize, SMEM_TOTAL_SCORE);
    cudaFuncSetAttribute(proj_mma_kernel,
                         cudaFuncAttributeMaxDynamicSharedMemorySize, 2 * PSTG);

    gate_init_kernel<<<(NL * NP * SS + 255) / 256, 256>>>(se);

    dim3 gproj(DH / 128, (QN * SS) / 128, NL);          // (4, 72, 3)
    proj_mma_kernel<<<gproj, 256, 2 * PSTG>>>(memory_,  fc1_w, fc1_b, 0);
    proj_mma_kernel<<<gproj, 256, 2 * PSTG>>>(features, fc1_w, fc1_b, 1);

    score_mma_kernel<<<dim3(KN * 2, QN, NL), 192, SMEM_TOTAL_SCORE>>>();

    mlp_kernel<<<dim3(DFFN / 128, (2 * NP) / 64, NL), 256>>>(
        fc2_w, fc2_b, bn2_g, bn2_b, fc3_w, bn1_g, bn1_b);

    final_kernel<<<(NP + 255) / 256, 256>>>(fc3_b, bn3_g, bn3_b, norm_g, norm_b, out);
}

// round 10
// speedup vs baseline: 2.4026x; 1.3315x over previous
#include <cuda_runtime.h>
#include <cuda_bf16.h>
#include <cuda_fp16.h>
#include <math.h>
#include <stdint.h>

typedef unsigned long long ull;

#define QN 48
#define KN 48
#define SS 192
#define DH 512
#define NL 3
#define DFFN 2048
#define NP (QN*KN)   /* 2304 */
#define KC 512       /* single fp16: K = D */
#define ROWB 1024    /* bytes per row = KC * 2 */

// ---------------- scratch (device globals) ----------------
__device__ uint4  g_Qc[(size_t)NL*QN*SS*ROWB/16];   // 28.3 MB fp16 (query)
__device__ uint4  g_Kc[(size_t)NL*KN*SS*ROWB/16];   // 28.3 MB fp16 (key)
__device__ float g_G [NL * SS * SS];
__device__ float g_X [NL * NP * 2 * SS];
__device__ float g_Z [NL * NP * 2];

__device__ __forceinline__ uint32_t smem_u32(const void* p) {
    uint32_t a;
    asm("{ .reg .u64 t; cvta.to.shared.u64 t, %1; cvt.u32.u64 %0, t; }" : "=r"(a) : "l"(p));
    return a;
}
// sign-aware float atomic max
__device__ __forceinline__ void atomicMaxFloat(float* addr, float val) {
    if (val >= 0.0f) atomicMax((int*)addr, __float_as_int(val));
    else             atomicMin((unsigned int*)addr, (unsigned int)__float_as_int(val));
}

// ---------------- mma / ldmatrix wrappers ----------------
__device__ __forceinline__ void mma_fp16(float* d, const uint32_t* a, uint32_t b0, uint32_t b1) {
    asm volatile("mma.sync.aligned.m16n8k16.row.col.f32.f16.f16.f32 "
                 "{%0,%1,%2,%3}, {%4,%5,%6,%7}, {%8,%9}, {%0,%1,%2,%3};"
                 : "+f"(d[0]), "+f"(d[1]), "+f"(d[2]), "+f"(d[3])
                 : "r"(a[0]), "r"(a[1]), "r"(a[2]), "r"(a[3]), "r"(b0), "r"(b1));
}
__device__ __forceinline__ void ldsm_x4(uint32_t* r, uint32_t addr) {
    asm volatile("ldmatrix.sync.aligned.m8n8.x4.shared.b16 {%0,%1,%2,%3}, [%4];"
                 : "=r"(r[0]), "=r"(r[1]), "=r"(r[2]), "=r"(r[3]) : "r"(addr));
}

// ---------------- kernel 1: gate sigmoid + zero Z + init row-max ----------------
__global__ void gate_init_kernel(const float* __restrict__ se) {
    int idx = blockIdx.x * blockDim.x + threadIdx.x;
    if (idx < NL * SS * SS) g_G[idx] = 1.0f / (1.0f + expf(-se[idx]));
    if (idx < NL * NP * 2)  g_Z[idx] = 0.0f;
    if (idx < NL * NP * SS) {
        int pair = idx / SS, off = idx - pair * SS;
        g_X[(size_t)pair * 2 * SS + off] = -3.402823466e38f;
    }
}

// ---------------- kernel 2: projection GEMM (HMMA, split-fp16 activations) ----------------
#define PCH 16        /* virtual 64-half chunks: 1024/64 */
#define PSTG 32768    /* stage: A 16K + W 16K */

__global__ void __launch_bounds__(256)
proj_mma_kernel(const float* __restrict__ A, const float* __restrict__ W,
                const float* __restrict__ bias, int dst)
{
    extern __shared__ __align__(128) char psm[];
    const int i = blockIdx.z;
    const int LDA = NL * DH;
    const float* Ab = A + i * DH;
    const float* Wb = W + (size_t)i * DH * DH;
    const float* bb = bias + i * DH;
    char* outBase = (char*)(dst ? g_Kc : g_Qc) + (size_t)(i * QN * SS) * ROWB;
    const int m0 = blockIdx.y * 128, n0 = blockIdx.x * 128;
    const int tid = threadIdx.x, wid = tid >> 5, lane = tid & 31;
    uint32_t sb = smem_u32(psm);
    const int mw = wid >> 2, nw = wid & 3;      // 2 (m) x 4 (n)
    const int m0w = mw * 64, n0w = nw * 32;

    uint32_t baseA[4], baseB[2];
#pragma unroll
    for (int mi = 0; mi < 4; mi++) {
        uint32_t row = (uint32_t)(m0w + mi * 16 + (lane & 15));
        uint32_t off = row * 128 + ((lane >> 4) << 4);
        baseA[mi] = off ^ ((off >> 3) & 0x70);
    }
#pragma unroll
    for (int nj = 0; nj < 2; nj++) {
        uint32_t row = (uint32_t)(n0w + nj * 16 + (lane & 7) + ((lane >> 4) << 3));
        uint32_t off = row * 128 + (((lane >> 3) & 1) << 4);
        baseB[nj] = 16384u + (off ^ ((off >> 3) & 0x70));
    }

    float acc[4][4][4];
#pragma unroll
    for (int mi = 0; mi < 4; mi++)
#pragma unroll
        for (int n8 = 0; n8 < 4; n8++)
#pragma unroll
            for (int j = 0; j < 4; j++) acc[mi][n8][j] = 0.0f;

    uint4 stg[8];

    auto load_chunk = [&](int c) {
        const int co0 = (c & 7) * 64;
        const bool lo = (c >= 8);
#pragma unroll
        for (int u = 0; u < 8; u++) {
            int idx = tid + u * 256;
            int isW = idx >= 1024;
            int j = idx & 1023;
            int r = j >> 3, g = j & 7;
            const float* src = isW ? (Wb + (size_t)(n0 + r) * DH  + co0 + g * 8)
                                   : (Ab + (size_t)(m0 + r) * LDA + co0 + g * 8);
            float4 f0 = *(const float4*)src;
            float4 f1 = *(const float4*)(src + 4);
            __half2 a0 = __floats2half2_rn(f0.x, f0.y);
            __half2 a1 = __floats2half2_rn(f0.z, f0.w);
            __half2 a2 = __floats2half2_rn(f1.x, f1.y);
            __half2 a3 = __floats2half2_rn(f1.z, f1.w);
            if (lo && !isW) {
                float2 r0 = __half22float2(a0), r1 = __half22float2(a1);
                float2 r2 = __half22float2(a2), r3 = __half22float2(a3);
                a0 = __floats2half2_rn(f0.x - r0.x, f0.y - r0.y);
                a1 = __floats2half2_rn(f0.z - r1.x, f0.w - r1.y);
                a2 = __floats2half2_rn(f1.x - r2.x, f1.y - r2.y);
                a3 = __floats2half2_rn(f1.z - r3.x, f1.w - r3.y);
            }
            stg[u].x = *reinterpret_cast<uint32_t*>(&a0);
            stg[u].y = *reinterpret_cast<uint32_t*>(&a1);
            stg[u].z = *reinterpret_cast<uint32_t*>(&a2);
            stg[u].w = *reinterpret_cast<uint32_t*>(&a3);
        }
    };
    auto store_chunk = [&](int buf) {
#pragma unroll
        for (int u = 0; u < 8; u++) {
            int idx = tid + u * 256;
            int isW = idx >= 1024;
            int j = idx & 1023;
            int r = j >> 3, g = j & 7;
            uint32_t off = (uint32_t)(r * 128 + g * 16);
            off ^= (off >> 3) & 0x70;
            *(uint4*)(psm + buf * PSTG + (isW ? 16384 : 0) + off) = stg[u];
        }
    };

    load_chunk(0);
    int buf = 0;
    for (int c = 0; c < PCH; c++) {
        store_chunk(buf);
        __syncthreads();
        if (c + 1 < PCH) load_chunk(c + 1);

        uint32_t stage = sb + buf * PSTG;
#pragma unroll
        for (int ks = 0; ks < 4; ks++) {
            uint32_t kx = (uint32_t)(ks << 5);
            uint32_t a[4][4], b[2][4];
#pragma unroll
            for (int mi = 0; mi < 4; mi++) ldsm_x4(a[mi], stage + (baseA[mi] ^ kx));
#pragma unroll
            for (int nj = 0; nj < 2; nj++) ldsm_x4(b[nj], stage + (baseB[nj] ^ kx));
#pragma unroll
            for (int mi = 0; mi < 4; mi++)
#pragma unroll
                for (int n8 = 0; n8 < 4; n8++)
                    mma_fp16(acc[mi][n8], a[mi], b[n8 >> 1][(n8 & 1) * 2], b[n8 >> 1][(n8 & 1) * 2 + 1]);
        }
        buf ^= 1;
    }

    const int g8 = lane >> 2, t4 = lane & 3;
    float bv[8];
#pragma unroll
    for (int n8 = 0; n8 < 4; n8++) {
        bv[n8 * 2]     = bb[n0 + n0w + n8 * 8 + t4 * 2];
        bv[n8 * 2 + 1] = bb[n0 + n0w + n8 * 8 + t4 * 2 + 1];
    }
#pragma unroll
    for (int mi = 0; mi < 4; mi++) {
        int r0 = m0 + m0w + mi * 16 + g8;
#pragma unroll
        for (int n8 = 0; n8 < 4; n8++) {
            int c0 = n0 + n0w + n8 * 8 + t4 * 2;
            __half2 v0 = __floats2half2_rn(acc[mi][n8][0] + bv[n8 * 2], acc[mi][n8][1] + bv[n8 * 2 + 1]);
            __half2 v1 = __floats2half2_rn(acc[mi][n8][2] + bv[n8 * 2], acc[mi][n8][3] + bv[n8 * 2 + 1]);
            *(__half2*)(outBase + (size_t)r0 * ROWB + c0 * 2)       = v0;
            *(__half2*)(outBase + (size_t)(r0 + 8) * ROWB + c0 * 2) = v1;
        }
    }
}

// ---------------- kernel 3: HMMA score GEMM + gate + dual max-pool ----------------
#define STAGES 3
#define CHUNK_B 128
#define NCHUNK 8
#define TILE_A 24576
#define STAGE_BYTES 36864
#define SM_BASE 1024
#define SMEM_TOTAL_SCORE (SM_BASE + STAGES * STAGE_BYTES)

__global__ void __launch_bounds__(192, 2)
score_mma_kernel()
{
    extern __shared__ __align__(128) char dsm[];
    const int i = blockIdx.z, q = blockIdx.y;
    const int k = blockIdx.x >> 1;
    const int h = blockIdx.x & 1;
    const int tid = threadIdx.x;
    const int wid = tid >> 5;
    const int lane = tid & 31;
    uint32_t sb = smem_u32(dsm);

    const char* aG = (const char*)g_Qc + (size_t)((i * QN + q) * SS) * ROWB;
    const char* bG = (const char*)g_Kc + (size_t)((i * KN + k) * SS + h * 96) * ROWB;

    const int mw = wid >> 1, nw = wid & 1;
    const int m0 = mw * 64;
    const int n0 = nw * 48;

    uint32_t baseA[4], baseB[3];
#pragma unroll
    for (int mi = 0; mi < 4; mi++) {
        uint32_t row = (uint32_t)(m0 + mi * 16 + (lane & 15));
        uint32_t off = row * 128 + ((lane >> 4) << 4);
        baseA[mi] = off ^ ((off >> 3) & 0x70);
    }
#pragma unroll
    for (int nt = 0; nt < 3; nt++) {
        uint32_t row = (uint32_t)(n0 + nt * 16 + (lane & 7) + ((lane >> 4) << 3));
        uint32_t off = row * 128 + (((lane >> 3) & 1) << 4);
        baseB[nt] = TILE_A + (off ^ ((off >> 3) & 0x70));
    }

    float acc[4][6][4];
#pragma unroll
    for (int mi = 0; mi < 4; mi++)
#pragma unroll
        for (int ni = 0; ni < 6; ni++)
#pragma unroll
            for (int j = 0; j < 4; j++) acc[mi][ni][j] = 0.0f;

    auto load_stage = [&](int c, int st) {
        uint32_t base = sb + SM_BASE + st * STAGE_BYTES;
#pragma unroll
        for (int l = 0; l < 12; l++) {
            int idx = tid + l * 192;
            int isB = idx >= 1536;
            int j2 = isB ? idx - 1536 : idx;
            int r = j2 >> 3, g = j2 & 7;
            uint32_t off = (uint32_t)(r * 128 + g * 16);
            off ^= (off >> 3) & 0x70;
            uint32_t dst = base + (isB ? TILE_A : 0) + off;
            const void* src = (const void*)((isB ? bG : aG) + (size_t)r * ROWB + c * CHUNK_B + g * 16);
            asm volatile("cp.async.cg.shared.global [%0], [%1], 16;" :: "r"(dst), "l"(src) : "memory");
        }
        asm volatile("cp.async.commit_group;" ::: "memory");
    };

    load_stage(0, 0);
    load_stage(1, 1);

    int stc = 0, stl = 2;
    for (int it = 0; it < NCHUNK; it++) {
        if (it == NCHUNK - 1) asm volatile("cp.async.wait_group 0;" ::: "memory");
        else                  asm volatile("cp.async.wait_group 1;" ::: "memory");
        __syncthreads();
        if (it + 2 < NCHUNK) load_stage(it + 2, stl);

        uint32_t stage = sb + SM_BASE + stc * STAGE_BYTES;
#pragma unroll
        for (int ks = 0; ks < 4; ks++) {
            uint32_t kx = (uint32_t)(ks << 5);
            uint32_t a[4][4], b[3][4];
#pragma unroll
            for (int mi = 0; mi < 4; mi++) ldsm_x4(a[mi], stage + (baseA[mi] ^ kx));
#pragma unroll
            for (int nt = 0; nt < 3; nt++) ldsm_x4(b[nt], stage + (baseB[nt] ^ kx));
#pragma unroll
            for (int mi = 0; mi < 4; mi++) {
#pragma unroll
                for (int nt = 0; nt < 3; nt++) {
                    mma_fp16(acc[mi][2 * nt],     a[mi], b[nt][0], b[nt][1]);
                    mma_fp16(acc[mi][2 * nt + 1], a[mi], b[nt][2], b[nt][3]);
                }
            }
        }
        if (++stc == STAGES) stc = 0;
        if (++stl == STAGES) stl = 0;
    }

    const float* gb = g_G + (size_t)i * SS * SS;
    const int g8 = lane >> 2, t4 = lane & 3;
    float rmax[8], cmax[12];
#pragma unroll
    for (int j = 0; j < 8; j++)  rmax[j] = -3.402823466e38f;
#pragma unroll
    for (int j = 0; j < 12; j++) cmax[j] = -3.402823466e38f;

#pragma unroll
    for (int mi = 0; mi < 4; mi++) {
        int r0 = m0 + mi * 16 + g8;
        int r1 = r0 + 8;
#pragma unroll
        for (int ni = 0; ni < 6; ni++) {
            int c0 = h * 96 + n0 + ni * 8 + t4 * 2;
            int c1 = c0 + 1;
            float v00 = acc[mi][ni][0] * __ldg(gb + (size_t)c0 * SS + r0);
            float v01 = acc[mi][ni][1] * __ldg(gb + (size_t)c1 * SS + r0);
            float v10 = acc[mi][ni][2] * __ldg(gb + (size_t)c0 * SS + r1);
            float v11 = acc[mi][ni][3] * __ldg(gb + (size_t)c1 * SS + r1);
            rmax[mi * 2]     = fmaxf(rmax[mi * 2],     fmaxf(v00, v01));
            rmax[mi * 2 + 1] = fmaxf(rmax[mi * 2 + 1], fmaxf(v10, v11));
            cmax[ni * 2]     = fmaxf(cmax[ni * 2],     fmaxf(v00, v10));
            cmax[ni * 2 + 1] = fmaxf(cmax[ni * 2 + 1], fmaxf(v01, v11));
        }
    }
#pragma unroll
    for (int m = 1; m <= 2; m <<= 1)
#pragma unroll
        for (int j = 0; j < 8; j++)
            rmax[j] = fmaxf(rmax[j], __shfl_xor_sync(0xffffffffu, rmax[j], m));
#pragma unroll
    for (int m = 4; m <= 16; m <<= 1)
#pragma unroll
        for (int j = 0; j < 12; j++)
            cmax[j] = fmaxf(cmax[j], __shfl_xor_sync(0xffffffffu, cmax[j], m));

    float* red1 = (float*)(dsm + SM_BASE);
    float* red2 = red1 + 2 * SS;
    if (t4 == 0) {
#pragma unroll
        for (int j = 0; j < 8; j++)
            red1[nw * SS + m0 + (j >> 1) * 16 + g8 + (j & 1) * 8] = rmax[j];
    }
    if (g8 == 0) {
#pragma unroll
        for (int j = 0; j < 12; j++)
            red2[mw * 96 + n0 + (j >> 1) * 8 + t4 * 2 + (j & 1)] = cmax[j];
    }
    __syncthreads();

    float* xo = g_X + ((size_t)i * NP + (size_t)q * KN + k) * (2 * SS);
    {
        float m = fmaxf(red1[tid], red1[SS + tid]);
        atomicMaxFloat(&xo[tid], m);
    }
    if (tid < 96) {
        float m = fmaxf(fmaxf(red2[tid], red2[96 + tid]), red2[192 + tid]);
        xo[SS + h * 96 + tid] = m;
    }
}

// ---------------- kernel 4: HMMA mlp: bn1 -> fc2 -> bn2 -> relu -> fc3 reduce ----------------
// split-fp16 activations (virtual K = 384), W2 rounded once.
#define MCH 6         /* 2 x 192/64 */
#define MSTG 32768    /* A 16K + W 16K */

__global__ void __launch_bounds__(256)
mlp_mma_kernel(const float* __restrict__ w2, const float* __restrict__ b2,
               const float* __restrict__ g2, const float* __restrict__ bb2,
               const float* __restrict__ w3,
               const float* __restrict__ g1, const float* __restrict__ bb1)
{
    extern __shared__ __align__(128) char msm[];
    __shared__ float zsh[128];
    const int i = blockIdx.z;
    const int row0 = blockIdx.y * 128;
    const int col0 = blockIdx.x * 128;
    const float scale = 1.0f / sqrtf(1.0f + 1e-5f);
    const float g1c = g1[i] * scale, b1v = bb1[i];
    const float* Xb  = g_X + (size_t)i * NP * 2 * SS;
    const float* W2b = w2  + (size_t)i * DFFN * SS;
    const int tid = threadIdx.x, wid = tid >> 5, lane = tid & 31;
    uint32_t sb = smem_u32(msm);
    const int mw = wid >> 2, nw = wid & 3;
    const int m0w = mw * 64, n0w = nw * 32;
    if (tid < 128) zsh[tid] = 0.0f;

    uint32_t baseA[4], baseB[2];
#pragma unroll
    for (int mi = 0; mi < 4; mi++) {
        uint32_t row = (uint32_t)(m0w + mi * 16 + (lane & 15));
        uint32_t off = row * 128 + ((lane >> 4) << 4);
        baseA[mi] = off ^ ((off >> 3) & 0x70);
    }
#pragma unroll
    for (int nj = 0; nj < 2; nj++) {
        uint32_t row = (uint32_t)(n0w + nj * 16 + (lane & 7) + ((lane >> 4) << 3));
        uint32_t off = row * 128 + (((lane >> 3) & 1) << 4);
        baseB[nj] = 16384u + (off ^ ((off >> 3) & 0x70));
    }

    float acc[4][4][4];
#pragma unroll
    for (int mi = 0; mi < 4; mi++)
#pragma unroll
        for (int n8 = 0; n8 < 4; n8++)
#pragma unroll
            for (int j = 0; j < 4; j++) acc[mi][n8][j] = 0.0f;

    uint4 stg[8];
    auto load_chunk = [&](int c) {
        int cm = c; if (cm >= 3) cm -= 3;
        const int kk0 = cm * 64;
        const bool lo = (c >= 3);
#pragma unroll
        for (int u = 0; u < 8; u++) {
            int idx = tid + u * 256;
            int isW = idx >= 1024;
            int j = idx & 1023;
            int r = j >> 3, g = j & 7;
            const float* src = isW ? (W2b + (size_t)(col0 + r) * SS + kk0 + g * 8)
                                   : (Xb  + (size_t)(row0 + r) * SS + kk0 + g * 8);
            float4 f0 = *(const float4*)src;
            float4 f1 = *(const float4*)(src + 4);
            if (!isW) {
                f0.x = f0.x * g1c + b1v; f0.y = f0.y * g1c + b1v;
                f0.z = f0.z * g1c + b1v; f0.w = f0.w * g1c + b1v;
                f1.x = f1.x * g1c + b1v; f1.y = f1.y * g1c + b1v;
                f1.z = f1.z * g1c + b1v; f1.w = f1.w * g1c + b1v;
            }
            __half2 a0 = __floats2half2_rn(f0.x, f0.y);
            __half2 a1 = __floats2half2_rn(f0.z, f0.w);
            __half2 a2 = __floats2half2_rn(f1.x, f1.y);
            __half2 a3 = __floats2half2_rn(f1.z, f1.w);
            if (lo && !isW) {
                float2 r0 = __half22float2(a0), r1 = __half22float2(a1);
                float2 r2 = __half22float2(a2), r3 = __half22float2(a3);
                a0 = __floats2half2_rn(f0.x - r0.x, f0.y - r0.y);
                a1 = __floats2half2_rn(f0.z - r1.x, f0.w - r1.y);
                a2 = __floats2half2_rn(f1.x - r2.x, f1.y - r2.y);
                a3 = __floats2half2_rn(f1.z - r3.x, f1.w - r3.y);
            }
            stg[u].x = *reinterpret_cast<uint32_t*>(&a0);
            stg[u].y = *reinterpret_cast<uint32_t*>(&a1);
            stg[u].z = *reinterpret_cast<uint32_t*>(&a2);
            stg[u].w = *reinterpret_cast<uint32_t*>(&a3);
        }
    };
    auto store_chunk = [&](int buf) {
#pragma unroll
        for (int u = 0; u < 8; u++) {
            int idx = tid + u * 256;
            int isW = idx >= 1024;
            int j = idx & 1023;
            int r = j >> 3, g = j & 7;
            uint32_t off = (uint32_t)(r * 128 + g * 16);
            off ^= (off >> 3) & 0x70;
            *(uint4*)(msm + buf * MSTG + (isW ? 16384 : 0) + off) = stg[u];
        }
    };

    load_chunk(0);
    int buf = 0;
    for (int c = 0; c < MCH; c++) {
        store_chunk(buf);
        __syncthreads();
        if (c + 1 < MCH) load_chunk(c + 1);

        uint32_t stage = sb + buf * MSTG;
#pragma unroll
        for (int ks = 0; ks < 4; ks++) {
            uint32_t kx = (uint32_t)(ks << 5);
            uint32_t a[4][4], b[2][4];
#pragma unroll
            for (int mi = 0; mi < 4; mi++) ldsm_x4(a[mi], stage + (baseA[mi] ^ kx));
#pragma unroll
            for (int nj = 0; nj < 2; nj++) ldsm_x4(b[nj], stage + (baseB[nj] ^ kx));
#pragma unroll
            for (int mi = 0; mi < 4; mi++)
#pragma unroll
                for (int n8 = 0; n8 < 4; n8++)
                    mma_fp16(acc[mi][n8], a[mi], b[n8 >> 1][(n8 & 1) * 2], b[n8 >> 1][(n8 & 1) * 2 + 1]);
        }
        buf ^= 1;
    }

    // epilogue: +b2, bn2, relu, *w3, reduce
    const int g8 = lane >> 2, t4 = lane & 3;
    float b2v[8], g2v[8], bb2v[8], w3v[8];
#pragma unroll
    for (int n8 = 0; n8 < 4; n8++) {
        int c0 = col0 + n0w + n8 * 8 + t4 * 2;
        b2v[n8*2]   = __ldg(b2  + (size_t)i * DFFN + c0);
        b2v[n8*2+1] = __ldg(b2  + (size_t)i * DFFN + c0 + 1);
        g2v[n8*2]   = __ldg(g2  + (size_t)i * DFFN + c0);
        g2v[n8*2+1] = __ldg(g2  + (size_t)i * DFFN + c0 + 1);
        bb2v[n8*2]   = __ldg(bb2 + (size_t)i * DFFN + c0);
        bb2v[n8*2+1] = __ldg(bb2 + (size_t)i * DFFN + c0 + 1);
        w3v[n8*2]   = __ldg(w3  + (size_t)i * DFFN + c0);
        w3v[n8*2+1] = __ldg(w3  + (size_t)i * DFFN + c0 + 1);
    }
    __syncthreads();   // zsh init visible (also covers last MMA stage reuse ordering)

#pragma unroll
    for (int mi = 0; mi < 4; mi++) {
        float zp0 = 0.0f, zp1 = 0.0f;
#pragma unroll
        for (int n8 = 0; n8 < 4; n8++) {
#pragma unroll
            for (int e = 0; e < 2; e++) {
                float y0 = acc[mi][n8][e]     + b2v[n8*2+e];
                float y1 = acc[mi][n8][2 + e] + b2v[n8*2+e];
                float yb0 = y0 * (g2v[n8*2+e] * scale) + bb2v[n8*2+e];
                float yb1 = y1 * (g2v[n8*2+e] * scale) + bb2v[n8*2+e];
                if (yb0 > 0.0f) zp0 += yb0 * w3v[n8*2+e];
                if (yb1 > 0.0f) zp1 += yb1 * w3v[n8*2+e];
            }
        }
        zp0 += __shfl_xor_sync(0xffffffffu, zp0, 1);
        zp0 += __shfl_xor_sync(0xffffffffu, zp0, 2);
        zp1 += __shfl_xor_sync(0xffffffffu, zp1, 1);
        zp1 += __shfl_xor_sync(0xffffffffu, zp1, 2);
        if (t4 == 0) {
            atomicAdd(&zsh[m0w + mi * 16 + g8], zp0);
            atomicAdd(&zsh[m0w + mi * 16 + g8 + 8], zp1);
        }
    }
    __syncthreads();
    if (tid < 128) atomicAdd(&g_Z[(size_t)i * NP * 2 + row0 + tid], zsh[tid]);
}

// ---------------- kernel 5: pair-sum, bn3, layer-sum, decoder norm ----------------
__global__ void final_kernel(const float* __restrict__ fc3_b,
                             const float* __restrict__ bn3_g, const float* __restrict__ bn3_b,
                             const float* __restrict__ norm_g, const float* __restrict__ norm_b,
                             float* __restrict__ out)
{
    int p = blockIdx.x * blockDim.x + threadIdx.x;
    if (p >= NP) return;
    const float scale = 1.0f / sqrtf(1.0f + 1e-5f);
    float acc = 0.0f;
#pragma unroll
    for (int i = 0; i < NL; i++) {
        float u = g_Z[i * NP * 2 + 2 * p] + g_Z[i * NP * 2 + 2 * p + 1] + 2.0f * fc3_b[i];
        acc += u * (bn3_g[i] * scale) + bn3_b[i];
    }
    out[p] = acc * (norm_g[0] * scale) + norm_b[0];
}

// ---------------- launch ----------------
extern "C" void kernel_launch(void* const* d_in, const int* in_sizes, int n_in,
                              void* d_out, int out_size)
{
    (void)in_sizes; (void)n_in; (void)out_size;
    const float* memory_  = (const float*)d_in[0];
    const float* features = (const float*)d_in[1];
    const float* fc1_w  = (const float*)d_in[2];
    const float* fc1_b  = (const float*)d_in[3];
    const float* se     = (const float*)d_in[4];
    const float* bn1_g  = (const float*)d_in[5];
    const float* bn1_b  = (const float*)d_in[6];
    const float* fc2_w  = (const float*)d_in[7];
    const float* fc2_b  = (const float*)d_in[8];
    const float* bn2_g  = (const float*)d_in[9];
    const float* bn2_b  = (const float*)d_in[10];
    const float* fc3_w  = (const float*)d_in[11];
    const float* fc3_b  = (const float*)d_in[12];
    const float* bn3_g  = (const float*)d_in[13];
    const float* bn3_b  = (const float*)d_in[14];
    const float* norm_g = (const float*)d_in[15];
    const float* norm_b = (const float*)d_in[16];
    float* out = (float*)d_out;

    cudaFuncSetAttribute(score_mma_kernel,
                         cudaFuncAttributeMaxDynamicSharedMemorySize, SMEM_TOTAL_SCORE);
    cudaFuncSetAttribute(proj_mma_kernel,
                         cudaFuncAttributeMaxDynamicSharedMemorySize, 2 * PSTG);
    cudaFuncSetAttribute(mlp_mma_kernel,
                         cudaFuncAttributeMaxDynamicSharedMemorySize, 2 * MSTG);

    gate_init_kernel<<<(NL * NP * SS + 255) / 256, 256>>>(se);

    dim3 gproj(DH / 128, (QN * SS) / 128, NL);          // (4, 72, 3)
    proj_mma_kernel<<<gproj, 256, 2 * PSTG>>>(memory_,  fc1_w, fc1_b, 0);
    proj_mma_kernel<<<gproj, 256, 2 * PSTG>>>(features, fc1_w, fc1_b, 1);

    score_mma_kernel<<<dim3(KN * 2, QN, NL), 192, SMEM_TOTAL_SCORE>>>();

    mlp_mma_kernel<<<dim3(DFFN / 128, (2 * NP) / 128, NL), 256, 2 * MSTG>>>(
        fc2_w, fc2_b, bn2_g, bn2_b, fc3_w, bn1_g, bn1_b);

    final_kernel<<<(NP + 255) / 256, 256>>>(fc3_b, bn3_g, bn3_b, norm_g, norm_b, out);
}

// round 11
// speedup vs baseline: 3.0163x; 1.2554x over previous
#include <cuda_runtime.h>
#include <cuda_bf16.h>
#include <cuda_fp16.h>
#include <math.h>
#include <stdint.h>

typedef unsigned long long ull;

#define QN 48
#define KN 48
#define SS 192
#define DH 512
#define NL 3
#define DFFN 2048
#define NP (QN*KN)   /* 2304 */
#define KC 512       /* single fp16: K = D */
#define ROWB 1024    /* bytes per row = KC * 2 */

// ---------------- scratch (device globals) ----------------
__device__ uint4  g_Qc[(size_t)NL*QN*SS*ROWB/16];   // 28.3 MB fp16 (query)
__device__ uint4  g_Kc[(size_t)NL*KN*SS*ROWB/16];   // 28.3 MB fp16 (key)
__device__ float g_G [NL * SS * SS];
__device__ float g_X [NL * NP * 2 * SS];
__device__ float g_Z [NL * NP * 2];

__device__ __forceinline__ uint32_t smem_u32(const void* p) {
    uint32_t a;
    asm("{ .reg .u64 t; cvta.to.shared.u64 t, %1; cvt.u32.u64 %0, t; }" : "=r"(a) : "l"(p));
    return a;
}
// sign-aware float atomic max
__device__ __forceinline__ void atomicMaxFloat(float* addr, float val) {
    if (val >= 0.0f) atomicMax((int*)addr, __float_as_int(val));
    else             atomicMin((unsigned int*)addr, (unsigned int)__float_as_int(val));
}

// ---------------- mma / ldmatrix wrappers ----------------
__device__ __forceinline__ void mma_fp16(float* d, const uint32_t* a, uint32_t b0, uint32_t b1) {
    asm volatile("mma.sync.aligned.m16n8k16.row.col.f32.f16.f16.f32 "
                 "{%0,%1,%2,%3}, {%4,%5,%6,%7}, {%8,%9}, {%0,%1,%2,%3};"
                 : "+f"(d[0]), "+f"(d[1]), "+f"(d[2]), "+f"(d[3])
                 : "r"(a[0]), "r"(a[1]), "r"(a[2]), "r"(a[3]), "r"(b0), "r"(b1));
}
__device__ __forceinline__ void ldsm_x4(uint32_t* r, uint32_t addr) {
    asm volatile("ldmatrix.sync.aligned.m8n8.x4.shared.b16 {%0,%1,%2,%3}, [%4];"
                 : "=r"(r[0]), "=r"(r[1]), "=r"(r[2]), "=r"(r[3]) : "r"(addr));
}

// ---------------- kernel 1: gate sigmoid + zero Z + init row-max ----------------
__global__ void gate_init_kernel(const float* __restrict__ se) {
    int idx = blockIdx.x * blockDim.x + threadIdx.x;
    if (idx < NL * SS * SS) g_G[idx] = 1.0f / (1.0f + expf(-se[idx]));
    if (idx < NL * NP * 2)  g_Z[idx] = 0.0f;
    if (idx < NL * NP * SS) {
        int pair = idx / SS, off = idx - pair * SS;
        g_X[(size_t)pair * 2 * SS + off] = -3.402823466e38f;
    }
}

// ---------------- kernel 2: projection GEMM (HMMA, single fp16) ----------------
#define PCH 8         /* 64-half chunks: 512/64 */
#define PSTG 32768    /* stage: A 16K + W 16K */

__global__ void __launch_bounds__(256)
proj_mma_kernel(const float* __restrict__ A, const float* __restrict__ W,
                const float* __restrict__ bias, int dst)
{
    extern __shared__ __align__(128) char psm[];
    const int i = blockIdx.z;
    const int LDA = NL * DH;
    const float* Ab = A + i * DH;
    const float* Wb = W + (size_t)i * DH * DH;
    const float* bb = bias + i * DH;
    char* outBase = (char*)(dst ? g_Kc : g_Qc) + (size_t)(i * QN * SS) * ROWB;
    const int m0 = blockIdx.y * 128, n0 = blockIdx.x * 128;
    const int tid = threadIdx.x, wid = tid >> 5, lane = tid & 31;
    uint32_t sb = smem_u32(psm);
    const int mw = wid >> 2, nw = wid & 3;      // 2 (m) x 4 (n)
    const int m0w = mw * 64, n0w = nw * 32;

    uint32_t baseA[4], baseB[2];
#pragma unroll
    for (int mi = 0; mi < 4; mi++) {
        uint32_t row = (uint32_t)(m0w + mi * 16 + (lane & 15));
        uint32_t off = row * 128 + ((lane >> 4) << 4);
        baseA[mi] = off ^ ((off >> 3) & 0x70);
    }
#pragma unroll
    for (int nj = 0; nj < 2; nj++) {
        uint32_t row = (uint32_t)(n0w + nj * 16 + (lane & 7) + ((lane >> 4) << 3));
        uint32_t off = row * 128 + (((lane >> 3) & 1) << 4);
        baseB[nj] = 16384u + (off ^ ((off >> 3) & 0x70));
    }

    float acc[4][4][4];
#pragma unroll
    for (int mi = 0; mi < 4; mi++)
#pragma unroll
        for (int n8 = 0; n8 < 4; n8++)
#pragma unroll
            for (int j = 0; j < 4; j++) acc[mi][n8][j] = 0.0f;

    uint4 stg[8];

    auto load_chunk = [&](int c) {
        const int co0 = c * 64;
#pragma unroll
        for (int u = 0; u < 8; u++) {
            int idx = tid + u * 256;
            int isW = idx >= 1024;
            int j = idx & 1023;
            int r = j >> 3, g = j & 7;
            const float* src = isW ? (Wb + (size_t)(n0 + r) * DH  + co0 + g * 8)
                                   : (Ab + (size_t)(m0 + r) * LDA + co0 + g * 8);
            float4 f0 = *(const float4*)src;
            float4 f1 = *(const float4*)(src + 4);
            __half2 a0 = __floats2half2_rn(f0.x, f0.y);
            __half2 a1 = __floats2half2_rn(f0.z, f0.w);
            __half2 a2 = __floats2half2_rn(f1.x, f1.y);
            __half2 a3 = __floats2half2_rn(f1.z, f1.w);
            stg[u].x = *reinterpret_cast<uint32_t*>(&a0);
            stg[u].y = *reinterpret_cast<uint32_t*>(&a1);
            stg[u].z = *reinterpret_cast<uint32_t*>(&a2);
            stg[u].w = *reinterpret_cast<uint32_t*>(&a3);
        }
    };
    auto store_chunk = [&](int buf) {
#pragma unroll
        for (int u = 0; u < 8; u++) {
            int idx = tid + u * 256;
            int isW = idx >= 1024;
            int j = idx & 1023;
            int r = j >> 3, g = j & 7;
            uint32_t off = (uint32_t)(r * 128 + g * 16);
            off ^= (off >> 3) & 0x70;
            *(uint4*)(psm + buf * PSTG + (isW ? 16384 : 0) + off) = stg[u];
        }
    };

    load_chunk(0);
    int buf = 0;
    for (int c = 0; c < PCH; c++) {
        store_chunk(buf);
        __syncthreads();
        if (c + 1 < PCH) load_chunk(c + 1);

        uint32_t stage = sb + buf * PSTG;
#pragma unroll
        for (int ks = 0; ks < 4; ks++) {
            uint32_t kx = (uint32_t)(ks << 5);
            uint32_t a[4][4], b[2][4];
#pragma unroll
            for (int mi = 0; mi < 4; mi++) ldsm_x4(a[mi], stage + (baseA[mi] ^ kx));
#pragma unroll
            for (int nj = 0; nj < 2; nj++) ldsm_x4(b[nj], stage + (baseB[nj] ^ kx));
#pragma unroll
            for (int mi = 0; mi < 4; mi++)
#pragma unroll
                for (int n8 = 0; n8 < 4; n8++)
                    mma_fp16(acc[mi][n8], a[mi], b[n8 >> 1][(n8 & 1) * 2], b[n8 >> 1][(n8 & 1) * 2 + 1]);
        }
        buf ^= 1;
    }

    const int g8 = lane >> 2, t4 = lane & 3;
    float bv[8];
#pragma unroll
    for (int n8 = 0; n8 < 4; n8++) {
        bv[n8 * 2]     = bb[n0 + n0w + n8 * 8 + t4 * 2];
        bv[n8 * 2 + 1] = bb[n0 + n0w + n8 * 8 + t4 * 2 + 1];
    }
#pragma unroll
    for (int mi = 0; mi < 4; mi++) {
        int r0 = m0 + m0w + mi * 16 + g8;
#pragma unroll
        for (int n8 = 0; n8 < 4; n8++) {
            int c0 = n0 + n0w + n8 * 8 + t4 * 2;
            __half2 v0 = __floats2half2_rn(acc[mi][n8][0] + bv[n8 * 2], acc[mi][n8][1] + bv[n8 * 2 + 1]);
            __half2 v1 = __floats2half2_rn(acc[mi][n8][2] + bv[n8 * 2], acc[mi][n8][3] + bv[n8 * 2 + 1]);
            *(__half2*)(outBase + (size_t)r0 * ROWB + c0 * 2)       = v0;
            *(__half2*)(outBase + (size_t)(r0 + 8) * ROWB + c0 * 2) = v1;
        }
    }
}

// ---------------- kernel 3: HMMA score GEMM + gate + dual max-pool ----------------
#define STAGES 3
#define CHUNK_B 128
#define NCHUNK 8
#define TILE_A 24576
#define STAGE_BYTES 36864
#define SM_BASE 1024
#define SMEM_TOTAL_SCORE (SM_BASE + STAGES * STAGE_BYTES)

__global__ void __launch_bounds__(192, 2)
score_mma_kernel()
{
    extern __shared__ __align__(128) char dsm[];
    const int i = blockIdx.z, q = blockIdx.y;
    const int k = blockIdx.x >> 1;
    const int h = blockIdx.x & 1;
    const int tid = threadIdx.x;
    const int wid = tid >> 5;
    const int lane = tid & 31;
    uint32_t sb = smem_u32(dsm);

    const char* aG = (const char*)g_Qc + (size_t)((i * QN + q) * SS) * ROWB;
    const char* bG = (const char*)g_Kc + (size_t)((i * KN + k) * SS + h * 96) * ROWB;

    const int mw = wid >> 1, nw = wid & 1;
    const int m0 = mw * 64;
    const int n0 = nw * 48;

    uint32_t baseA[4], baseB[3];
#pragma unroll
    for (int mi = 0; mi < 4; mi++) {
        uint32_t row = (uint32_t)(m0 + mi * 16 + (lane & 15));
        uint32_t off = row * 128 + ((lane >> 4) << 4);
        baseA[mi] = off ^ ((off >> 3) & 0x70);
    }
#pragma unroll
    for (int nt = 0; nt < 3; nt++) {
        uint32_t row = (uint32_t)(n0 + nt * 16 + (lane & 7) + ((lane >> 4) << 3));
        uint32_t off = row * 128 + (((lane >> 3) & 1) << 4);
        baseB[nt] = TILE_A + (off ^ ((off >> 3) & 0x70));
    }

    float acc[4][6][4];
#pragma unroll
    for (int mi = 0; mi < 4; mi++)
#pragma unroll
        for (int ni = 0; ni < 6; ni++)
#pragma unroll
            for (int j = 0; j < 4; j++) acc[mi][ni][j] = 0.0f;

    auto load_stage = [&](int c, int st) {
        uint32_t base = sb + SM_BASE + st * STAGE_BYTES;
#pragma unroll
        for (int l = 0; l < 12; l++) {
            int idx = tid + l * 192;
            int isB = idx >= 1536;
            int j2 = isB ? idx - 1536 : idx;
            int r = j2 >> 3, g = j2 & 7;
            uint32_t off = (uint32_t)(r * 128 + g * 16);
            off ^= (off >> 3) & 0x70;
            uint32_t dst = base + (isB ? TILE_A : 0) + off;
            const void* src = (const void*)((isB ? bG : aG) + (size_t)r * ROWB + c * CHUNK_B + g * 16);
            asm volatile("cp.async.cg.shared.global [%0], [%1], 16;" :: "r"(dst), "l"(src) : "memory");
        }
        asm volatile("cp.async.commit_group;" ::: "memory");
    };

    load_stage(0, 0);
    load_stage(1, 1);

    int stc = 0, stl = 2;
    for (int it = 0; it < NCHUNK; it++) {
        if (it == NCHUNK - 1) asm volatile("cp.async.wait_group 0;" ::: "memory");
        else                  asm volatile("cp.async.wait_group 1;" ::: "memory");
        __syncthreads();
        if (it + 2 < NCHUNK) load_stage(it + 2, stl);

        uint32_t stage = sb + SM_BASE + stc * STAGE_BYTES;
#pragma unroll
        for (int ks = 0; ks < 4; ks++) {
            uint32_t kx = (uint32_t)(ks << 5);
            uint32_t a[4][4], b[3][4];
#pragma unroll
            for (int mi = 0; mi < 4; mi++) ldsm_x4(a[mi], stage + (baseA[mi] ^ kx));
#pragma unroll
            for (int nt = 0; nt < 3; nt++) ldsm_x4(b[nt], stage + (baseB[nt] ^ kx));
#pragma unroll
            for (int mi = 0; mi < 4; mi++) {
#pragma unroll
                for (int nt = 0; nt < 3; nt++) {
                    mma_fp16(acc[mi][2 * nt],     a[mi], b[nt][0], b[nt][1]);
                    mma_fp16(acc[mi][2 * nt + 1], a[mi], b[nt][2], b[nt][3]);
                }
            }
        }
        if (++stc == STAGES) stc = 0;
        if (++stl == STAGES) stl = 0;
    }

    const float* gb = g_G + (size_t)i * SS * SS;
    const int g8 = lane >> 2, t4 = lane & 3;
    float rmax[8], cmax[12];
#pragma unroll
    for (int j = 0; j < 8; j++)  rmax[j] = -3.402823466e38f;
#pragma unroll
    for (int j = 0; j < 12; j++) cmax[j] = -3.402823466e38f;

#pragma unroll
    for (int mi = 0; mi < 4; mi++) {
        int r0 = m0 + mi * 16 + g8;
        int r1 = r0 + 8;
#pragma unroll
        for (int ni = 0; ni < 6; ni++) {
            int c0 = h * 96 + n0 + ni * 8 + t4 * 2;
            int c1 = c0 + 1;
            float v00 = acc[mi][ni][0] * __ldg(gb + (size_t)c0 * SS + r0);
            float v01 = acc[mi][ni][1] * __ldg(gb + (size_t)c1 * SS + r0);
            float v10 = acc[mi][ni][2] * __ldg(gb + (size_t)c0 * SS + r1);
            float v11 = acc[mi][ni][3] * __ldg(gb + (size_t)c1 * SS + r1);
            rmax[mi * 2]     = fmaxf(rmax[mi * 2],     fmaxf(v00, v01));
            rmax[mi * 2 + 1] = fmaxf(rmax[mi * 2 + 1], fmaxf(v10, v11));
            cmax[ni * 2]     = fmaxf(cmax[ni * 2],     fmaxf(v00, v10));
            cmax[ni * 2 + 1] = fmaxf(cmax[ni * 2 + 1], fmaxf(v01, v11));
        }
    }
#pragma unroll
    for (int m = 1; m <= 2; m <<= 1)
#pragma unroll
        for (int j = 0; j < 8; j++)
            rmax[j] = fmaxf(rmax[j], __shfl_xor_sync(0xffffffffu, rmax[j], m));
#pragma unroll
    for (int m = 4; m <= 16; m <<= 1)
#pragma unroll
        for (int j = 0; j < 12; j++)
            cmax[j] = fmaxf(cmax[j], __shfl_xor_sync(0xffffffffu, cmax[j], m));

    float* red1 = (float*)(dsm + SM_BASE);
    float* red2 = red1 + 2 * SS;
    if (t4 == 0) {
#pragma unroll
        for (int j = 0; j < 8; j++)
            red1[nw * SS + m0 + (j >> 1) * 16 + g8 + (j & 1) * 8] = rmax[j];
    }
    if (g8 == 0) {
#pragma unroll
        for (int j = 0; j < 12; j++)
            red2[mw * 96 + n0 + (j >> 1) * 8 + t4 * 2 + (j & 1)] = cmax[j];
    }
    __syncthreads();

    float* xo = g_X + ((size_t)i * NP + (size_t)q * KN + k) * (2 * SS);
    {
        float m = fmaxf(red1[tid], red1[SS + tid]);
        atomicMaxFloat(&xo[tid], m);
    }
    if (tid < 96) {
        float m = fmaxf(fmaxf(red2[tid], red2[96 + tid]), red2[192 + tid]);
        xo[SS + h * 96 + tid] = m;
    }
}

// ---------------- kernel 4: HMMA mlp: bn1 -> fc2 -> bn2 -> relu -> fc3 reduce ----------------
// single fp16 (K = 192), W2 rounded once.
#define MCH 3         /* 192/64 */
#define MSTG 32768    /* A 16K + W 16K */

__global__ void __launch_bounds__(256)
mlp_mma_kernel(const float* __restrict__ w2, const float* __restrict__ b2,
               const float* __restrict__ g2, const float* __restrict__ bb2,
               const float* __restrict__ w3,
               const float* __restrict__ g1, const float* __restrict__ bb1)
{
    extern __shared__ __align__(128) char msm[];
    __shared__ float zsh[128];
    const int i = blockIdx.z;
    const int row0 = blockIdx.y * 128;
    const int col0 = blockIdx.x * 128;
    const float scale = 1.0f / sqrtf(1.0f + 1e-5f);
    const float g1c = g1[i] * scale, b1v = bb1[i];
    const float* Xb  = g_X + (size_t)i * NP * 2 * SS;
    const float* W2b = w2  + (size_t)i * DFFN * SS;
    const int tid = threadIdx.x, wid = tid >> 5, lane = tid & 31;
    uint32_t sb = smem_u32(msm);
    const int mw = wid >> 2, nw = wid & 3;
    const int m0w = mw * 64, n0w = nw * 32;
    if (tid < 128) zsh[tid] = 0.0f;

    uint32_t baseA[4], baseB[2];
#pragma unroll
    for (int mi = 0; mi < 4; mi++) {
        uint32_t row = (uint32_t)(m0w + mi * 16 + (lane & 15));
        uint32_t off = row * 128 + ((lane >> 4) << 4);
        baseA[mi] = off ^ ((off >> 3) & 0x70);
    }
#pragma unroll
    for (int nj = 0; nj < 2; nj++) {
        uint32_t row = (uint32_t)(n0w + nj * 16 + (lane & 7) + ((lane >> 4) << 3));
        uint32_t off = row * 128 + (((lane >> 3) & 1) << 4);
        baseB[nj] = 16384u + (off ^ ((off >> 3) & 0x70));
    }

    float acc[4][4][4];
#pragma unroll
    for (int mi = 0; mi < 4; mi++)
#pragma unroll
        for (int n8 = 0; n8 < 4; n8++)
#pragma unroll
            for (int j = 0; j < 4; j++) acc[mi][n8][j] = 0.0f;

    uint4 stg[8];
    auto load_chunk = [&](int c) {
        const int kk0 = c * 64;
#pragma unroll
        for (int u = 0; u < 8; u++) {
            int idx = tid + u * 256;
            int isW = idx >= 1024;
            int j = idx & 1023;
            int r = j >> 3, g = j & 7;
            const float* src = isW ? (W2b + (size_t)(col0 + r) * SS + kk0 + g * 8)
                                   : (Xb  + (size_t)(row0 + r) * SS + kk0 + g * 8);
            float4 f0 = *(const float4*)src;
            float4 f1 = *(const float4*)(src + 4);
            if (!isW) {
                f0.x = f0.x * g1c + b1v; f0.y = f0.y * g1c + b1v;
                f0.z = f0.z * g1c + b1v; f0.w = f0.w * g1c + b1v;
                f1.x = f1.x * g1c + b1v; f1.y = f1.y * g1c + b1v;
                f1.z = f1.z * g1c + b1v; f1.w = f1.w * g1c + b1v;
            }
            __half2 a0 = __floats2half2_rn(f0.x, f0.y);
            __half2 a1 = __floats2half2_rn(f0.z, f0.w);
            __half2 a2 = __floats2half2_rn(f1.x, f1.y);
            __half2 a3 = __floats2half2_rn(f1.z, f1.w);
            stg[u].x = *reinterpret_cast<uint32_t*>(&a0);
            stg[u].y = *reinterpret_cast<uint32_t*>(&a1);
            stg[u].z = *reinterpret_cast<uint32_t*>(&a2);
            stg[u].w = *reinterpret_cast<uint32_t*>(&a3);
        }
    };
    auto store_chunk = [&](int buf) {
#pragma unroll
        for (int u = 0; u < 8; u++) {
            int idx = tid + u * 256;
            int isW = idx >= 1024;
            int j = idx & 1023;
            int r = j >> 3, g = j & 7;
            uint32_t off = (uint32_t)(r * 128 + g * 16);
            off ^= (off >> 3) & 0x70;
            *(uint4*)(msm + buf * MSTG + (isW ? 16384 : 0) + off) = stg[u];
        }
    };

    load_chunk(0);
    int buf = 0;
    for (int c = 0; c < MCH; c++) {
        store_chunk(buf);
        __syncthreads();
        if (c + 1 < MCH) load_chunk(c + 1);

        uint32_t stage = sb + buf * MSTG;
#pragma unroll
        for (int ks = 0; ks < 4; ks++) {
            uint32_t kx = (uint32_t)(ks << 5);
            uint32_t a[4][4], b[2][4];
#pragma unroll
            for (int mi = 0; mi < 4; mi++) ldsm_x4(a[mi], stage + (baseA[mi] ^ kx));
#pragma unroll
            for (int nj = 0; nj < 2; nj++) ldsm_x4(b[nj], stage + (baseB[nj] ^ kx));
#pragma unroll
            for (int mi = 0; mi < 4; mi++)
#pragma unroll
                for (int n8 = 0; n8 < 4; n8++)
                    mma_fp16(acc[mi][n8], a[mi], b[n8 >> 1][(n8 & 1) * 2], b[n8 >> 1][(n8 & 1) * 2 + 1]);
        }
        buf ^= 1;
    }

    // epilogue: +b2, bn2, relu, *w3, reduce
    const int g8 = lane >> 2, t4 = lane & 3;
    float b2v[8], g2v[8], bb2v[8], w3v[8];
#pragma unroll
    for (int n8 = 0; n8 < 4; n8++) {
        int c0 = col0 + n0w + n8 * 8 + t4 * 2;
        b2v[n8*2]   = __ldg(b2  + (size_t)i * DFFN + c0);
        b2v[n8*2+1] = __ldg(b2  + (size_t)i * DFFN + c0 + 1);
        g2v[n8*2]   = __ldg(g2  + (size_t)i * DFFN + c0);
        g2v[n8*2+1] = __ldg(g2  + (size_t)i * DFFN + c0 + 1);
        bb2v[n8*2]   = __ldg(bb2 + (size_t)i * DFFN + c0);
        bb2v[n8*2+1] = __ldg(bb2 + (size_t)i * DFFN + c0 + 1);
        w3v[n8*2]   = __ldg(w3  + (size_t)i * DFFN + c0);
        w3v[n8*2+1] = __ldg(w3  + (size_t)i * DFFN + c0 + 1);
    }
    __syncthreads();

#pragma unroll
    for (int mi = 0; mi < 4; mi++) {
        float zp0 = 0.0f, zp1 = 0.0f;
#pragma unroll
        for (int n8 = 0; n8 < 4; n8++) {
#pragma unroll
            for (int e = 0; e < 2; e++) {
                float y0 = acc[mi][n8][e]     + b2v[n8*2+e];
                float y1 = acc[mi][n8][2 + e] + b2v[n8*2+e];
                float yb0 = y0 * (g2v[n8*2+e] * scale) + bb2v[n8*2+e];
                float yb1 = y1 * (g2v[n8*2+e] * scale) + bb2v[n8*2+e];
                if (yb0 > 0.0f) zp0 += yb0 * w3v[n8*2+e];
                if (yb1 > 0.0f) zp1 += yb1 * w3v[n8*2+e];
            }
        }
        zp0 += __shfl_xor_sync(0xffffffffu, zp0, 1);
        zp0 += __shfl_xor_sync(0xffffffffu, zp0, 2);
        zp1 += __shfl_xor_sync(0xffffffffu, zp1, 1);
        zp1 += __shfl_xor_sync(0xffffffffu, zp1, 2);
        if (t4 == 0) {
            atomicAdd(&zsh[m0w + mi * 16 + g8], zp0);
            atomicAdd(&zsh[m0w + mi * 16 + g8 + 8], zp1);
        }
    }
    __syncthreads();
    if (tid < 128) atomicAdd(&g_Z[(size_t)i * NP * 2 + row0 + tid], zsh[tid]);
}

// ---------------- kernel 5: pair-sum, bn3, layer-sum, decoder norm ----------------
__global__ void final_kernel(const float* __restrict__ fc3_b,
                             const float* __restrict__ bn3_g, const float* __restrict__ bn3_b,
                             const float* __restrict__ norm_g, const float* __restrict__ norm_b,
                             float* __restrict__ out)
{
    int p = blockIdx.x * blockDim.x + threadIdx.x;
    if (p >= NP) return;
    const float scale = 1.0f / sqrtf(1.0f + 1e-5f);
    float acc = 0.0f;
#pragma unroll
    for (int i = 0; i < NL; i++) {
        float u = g_Z[i * NP * 2 + 2 * p] + g_Z[i * NP * 2 + 2 * p + 1] + 2.0f * fc3_b[i];
        acc += u * (bn3_g[i] * scale) + bn3_b[i];
    }
    out[p] = acc * (norm_g[0] * scale) + norm_b[0];
}

// ---------------- launch ----------------
extern "C" void kernel_launch(void* const* d_in, const int* in_sizes, int n_in,
                              void* d_out, int out_size)
{
    (void)in_sizes; (void)n_in; (void)out_size;
    const float* memory_  = (const float*)d_in[0];
    const float* features = (const float*)d_in[1];
    const float* fc1_w  = (const float*)d_in[2];
    const float* fc1_b  = (const float*)d_in[3];
    const float* se     = (const float*)d_in[4];
    const float* bn1_g  = (const float*)d_in[5];
    const float* bn1_b  = (const float*)d_in[6];
    const float* fc2_w  = (const float*)d_in[7];
    const float* fc2_b  = (const float*)d_in[8];
    const float* bn2_g  = (const float*)d_in[9];
    const float* bn2_b  = (const float*)d_in[10];
    const float* fc3_w  = (const float*)d_in[11];
    const float* fc3_b  = (const float*)d_in[12];
    const float* bn3_g  = (const float*)d_in[13];
    const float* bn3_b  = (const float*)d_in[14];
    const float* norm_g = (const float*)d_in[15];
    const float* norm_b = (const float*)d_in[16];
    float* out = (float*)d_out;

    cudaFuncSetAttribute(score_mma_kernel,
                         cudaFuncAttributeMaxDynamicSharedMemorySize, SMEM_TOTAL_SCORE);
    cudaFuncSetAttribute(proj_mma_kernel,
                         cudaFuncAttributeMaxDynamicSharedMemorySize, 2 * PSTG);
    cudaFuncSetAttribute(mlp_mma_kernel,
                         cudaFuncAttributeMaxDynamicSharedMemorySize, 2 * MSTG);

    gate_init_kernel<<<(NL * NP * SS + 255) / 256, 256>>>(se);

    dim3 gproj(DH / 128, (QN * SS) / 128, NL);          // (4, 72, 3)
    proj_mma_kernel<<<gproj, 256, 2 * PSTG>>>(memory_,  fc1_w, fc1_b, 0);
    proj_mma_kernel<<<gproj, 256, 2 * PSTG>>>(features, fc1_w, fc1_b, 1);

    score_mma_kernel<<<dim3(KN * 2, QN, NL), 192, SMEM_TOTAL_SCORE>>>();

    mlp_mma_kernel<<<dim3(DFFN / 128, (2 * NP) / 128, NL), 256, 2 * MSTG>>>(
        fc2_w, fc2_b, bn2_g, bn2_b, fc3_w, bn1_g, bn1_b);

    final_kernel<<<(NP + 255) / 256, 256>>>(fc3_b, bn3_g, bn3_b, norm_g, norm_b, out);
}